// round 6
// baseline (speedup 1.0000x reference)
#include <cuda_runtime.h>
#include <cuda_bf16.h>
#include <cstdint>

#define NB    65536
#define DIM   256
#define HID   64
#define ACT   18
#define NEXP  8
#define ROWS  64
#define NTHR  128
#define HPAD  72        // halves per row stride (144B) -> conflict-free ldmatrix

// smem byte offsets
#define SH_HI  0
#define SH_LO  9216
#define SW_BUF 18432        // two W buffers, each: hi 9216 + lo 9216 = 18432
#define SWSZ   18432
#define SBIAS  (SW_BUF + 2 * SWSZ)   // 55296; 352 floats
#define SMEM_TOTAL (SBIAS + 1408)    // 56704

// ---------------- scratch ----------------
#define HB 64           // hist blocks (1024 rm elems each)
__device__ int g_part[HB * NEXP];
__device__ int g_base[HB * NEXP];
__device__ int g_offsets[NEXP + 1];
__device__ int g_perm[NB];
// preconverted weights: per expert 9 slots (W1 c0..c3, W2..W5, W6) of 8192 bf16:
// hi plane [0,4096), lo plane [4096,8192); layout [n][64 k]
__device__ __align__(16) __nv_bfloat16 g_w[NEXP * 9 * 8192];

#define WCONV_TOTAL (NEXP * 34816)
#define WB ((WCONV_TOTAL + 1023) / 1024)   // 272 wconv blocks (4 elems/thread)

// ---------------- fused hist + wconv ----------------
__global__ void k_pre1(const int4* __restrict__ rm,
                       const float* __restrict__ W1, const float* __restrict__ W2,
                       const float* __restrict__ W3, const float* __restrict__ W4,
                       const float* __restrict__ W5, const float* __restrict__ W6) {
    int b = blockIdx.x, t = threadIdx.x;
    if (b < HB) {
        __shared__ int s_cnt[NEXP];
        if (t < NEXP) s_cnt[t] = 0;
        __syncthreads();
        int4 v = rm[b * 256 + t];
        int vv[4] = { v.x, v.y, v.z, v.w };
        #pragma unroll
        for (int r = 0; r < 4; r++) {
            unsigned m = __match_any_sync(0xffffffffu, vv[r]);
            if ((t & 31) == __ffs(m) - 1) atomicAdd(&s_cnt[vv[r]], __popc(m));
        }
        __syncthreads();
        if (t < NEXP) g_part[b * NEXP + t] = s_cnt[t];
    } else {
        int wb = b - HB;
        #pragma unroll
        for (int j = 0; j < 4; j++) {
            int idx = wb * 1024 + j * 256 + t;
            if (idx >= WCONV_TOTAL) break;
            int e = idx / 34816, r = idx % 34816;
            float w;
            int dst;
            if (r < 16384) {
                int c = r >> 12, nk = r & 4095, n = nk >> 6, k = nk & 63;
                w = W1[((size_t)e * 256 + c * 64 + k) * 64 + n];
                dst = (e * 9 + c) * 8192 + nk;
            } else if (r < 32768) {
                int l = (r - 16384) >> 12, nk = (r - 16384) & 4095, n = nk >> 6, k = nk & 63;
                const float* Wl = (l == 0) ? W2 : (l == 1) ? W3 : (l == 2) ? W4 : W5;
                w = Wl[((size_t)e * 64 + k) * 64 + n];
                dst = (e * 9 + 4 + l) * 8192 + nk;
            } else {
                int nk = r - 32768, n = nk >> 6, k = nk & 63;
                w = (n < ACT) ? W6[((size_t)e * 64 + k) * ACT + n] : 0.f;
                dst = (e * 9 + 8) * 8192 + nk;
            }
            __nv_bfloat16 h = __float2bfloat16(w);
            g_w[dst] = h;
            g_w[dst + 4096] = __float2bfloat16(w - __bfloat162float(h));
        }
    }
}

// ---------------- prefix: offsets + per-block bases ----------------
__global__ void k_pre2() {
    __shared__ int cnts[NEXP];
    int t = threadIdx.x;
    if (t < NEXP) {
        int run = 0;
        for (int b = 0; b < HB; b++) run += g_part[b * NEXP + t];
        cnts[t] = run;
    }
    __syncthreads();
    if (t == 0) {
        int off = 0;
        for (int e = 0; e < NEXP; e++) { g_offsets[e] = off; off += cnts[e]; }
        g_offsets[NEXP] = off;
    }
    __syncthreads();
    if (t < NEXP) {
        int run = g_offsets[t];
        for (int b = 0; b < HB; b++) {
            g_base[b * NEXP + t] = run;
            run += g_part[b * NEXP + t];
        }
    }
}

// ---------------- scatter (no global atomics) ----------------
__global__ void k_scatter(const int4* __restrict__ rm) {
    __shared__ int s_cnt[NEXP];
    int b = blockIdx.x, t = threadIdx.x;
    if (t < NEXP) s_cnt[t] = 0;
    __syncthreads();
    int4 v = rm[b * 256 + t];
    int vv[4] = { v.x, v.y, v.z, v.w };
    unsigned lt = (1u << (t & 31)) - 1u;
    int i4 = (b * 256 + t) * 4;
    #pragma unroll
    for (int r = 0; r < 4; r++) {
        unsigned m = __match_any_sync(0xffffffffu, vv[r]);
        int leader = __ffs(m) - 1;
        int base = 0;
        if ((t & 31) == leader) base = atomicAdd(&s_cnt[vv[r]], __popc(m));
        base = __shfl_sync(0xffffffffu, base, leader);
        g_perm[g_base[b * NEXP + vv[r]] + base + __popc(m & lt)] = i4 + r;
    }
}

// ---------------- helpers ----------------
__device__ __forceinline__ uint32_t smem_u32(const void* p) {
    uint32_t a;
    asm("{ .reg .u64 t; cvta.to.shared.u64 t, %1; cvt.u32.u64 %0, t; }" : "=r"(a) : "l"(p));
    return a;
}
__device__ __forceinline__ uint32_t bf2(float a, float b) {
    uint32_t r;
    asm("cvt.rn.bf16x2.f32 %0, %1, %2;" : "=r"(r) : "f"(b), "f"(a));
    return r;
}
__device__ __forceinline__ float bfr(float x) {
    __nv_bfloat16 h = __float2bfloat16(x);
    return x - __bfloat162float(h);
}
#define CP16(dst, src) \
    asm volatile("cp.async.ca.shared.global [%0], [%1], 16;" :: "r"(dst), "l"(src))
#define CP_COMMIT() asm volatile("cp.async.commit_group;" ::: "memory")
#define CP_WAIT0()  asm volatile("cp.async.wait_group 0;" ::: "memory")

#define LDSM4(d, addr) \
    asm volatile("ldmatrix.sync.aligned.m8n8.x4.shared.b16 {%0,%1,%2,%3}, [%4];" \
        : "=r"((d)[0]), "=r"((d)[1]), "=r"((d)[2]), "=r"((d)[3]) : "r"(addr))

#define MMA(c, a, b0, b1) \
    asm volatile("mma.sync.aligned.m16n8k16.row.col.f32.bf16.bf16.f32 " \
        "{%0,%1,%2,%3},{%4,%5,%6,%7},{%8,%9},{%0,%1,%2,%3};" \
        : "+f"((c)[0]), "+f"((c)[1]), "+f"((c)[2]), "+f"((c)[3]) \
        : "r"((a)[0]), "r"((a)[1]), "r"((a)[2]), "r"((a)[3]), "r"(b0), "r"(b1))

// stage one weight slot (hi+lo planes) via cp.async; nW = rows (64 or 32)
__device__ __forceinline__ void stageW(uint32_t swb, const __nv_bfloat16* gw,
                                       int tid, int nW) {
    const char* src = (const char*)gw;
    int total = nW * 8;
    #pragma unroll 4
    for (int i = tid; i < total; i += NTHR) {
        int n = i >> 3, j = i & 7;
        uint32_t d = n * (HPAD * 2) + j * 16;
        int s = (n * 64 + j * 8) * 2;
        CP16(swb + d, src + s);
        CP16(swb + 9216 + d, src + 8192 + s);
    }
}

// full 64x64 MMA block (3-term split)
#define MMA_LAYER(accv, shi_, slo_, wb_) do {                                  \
    _Pragma("unroll")                                                          \
    for (int ks = 0; ks < 4; ks++) {                                           \
        uint32_t k0 = ks * 16;                                                 \
        uint32_t aoff = (aRow * HPAD + k0 + aKof) * 2;                         \
        uint32_t ahi[4], alo[4];                                               \
        LDSM4(ahi, (shi_) + aoff);                                             \
        LDSM4(alo, (slo_) + aoff);                                             \
        _Pragma("unroll")                                                      \
        for (int p = 0; p < 4; p++) {                                          \
            uint32_t boff = ((p * 16 + bRowL) * HPAD + k0 + bKof) * 2;         \
            uint32_t bh[4], bl[4];                                             \
            LDSM4(bh, (wb_) + boff);                                           \
            LDSM4(bl, (wb_) + 9216 + boff);                                    \
            MMA(accv[2 * p],     ahi, bh[0], bh[1]);                           \
            MMA(accv[2 * p],     ahi, bl[0], bl[1]);                           \
            MMA(accv[2 * p],     alo, bh[0], bh[1]);                           \
            MMA(accv[2 * p + 1], ahi, bh[2], bh[3]);                           \
            MMA(accv[2 * p + 1], ahi, bl[2], bl[3]);                           \
            MMA(accv[2 * p + 1], alo, bh[2], bh[3]);                           \
        }                                                                      \
    }                                                                          \
} while (0)

// ---------------- fused MoE (pipelined) ----------------
__global__ void __launch_bounds__(NTHR, 4) k_moe(
    const float* __restrict__ X,
    const float* __restrict__ b1, const float* __restrict__ b2,
    const float* __restrict__ b3, const float* __restrict__ b4,
    const float* __restrict__ b5, const float* __restrict__ b6,
    float* __restrict__ out)
{
    extern __shared__ char smem[];
    const int tid = threadIdx.x, wid = tid >> 5, lane = tid & 31;
    const int e = blockIdx.y, tile = blockIdx.x;
    const int off = g_offsets[e];
    const int cnt = g_offsets[e + 1] - off;
    if (tile * ROWS >= cnt) return;
    const int nrows = min(ROWS, cnt - tile * ROWS);

    const uint32_t sb  = smem_u32(smem);
    const uint32_t shi = sb + SH_HI, slo = sb + SH_LO;
    const uint32_t wbuf[2] = { sb + SW_BUF, sb + SW_BUF + SWSZ };
    float* sB = (float*)(smem + SBIAS);

    const __nv_bfloat16* gwE = g_w + (size_t)e * 9 * 8192;

    // prologue: prefetch W slot 0 into buf0
    stageW(wbuf[0], gwE, tid, 64);
    CP_COMMIT();

    // bias preload
    if (tid < 64) {
        sB[tid]       = b1[e * HID + tid];
        sB[64 + tid]  = b2[e * HID + tid];
        sB[128 + tid] = b3[e * HID + tid];
        sB[192 + tid] = b4[e * HID + tid];
        sB[256 + tid] = b5[e * HID + tid];
    }
    if (tid < 32) sB[320 + tid] = (tid < ACT) ? b6[e * ACT + tid] : 0.f;

    const int rbase = wid * 16;
    const uint32_t aRow  = (uint32_t)(rbase + (lane & 7) + ((lane >> 3) & 1) * 8);
    const uint32_t aKof  = ((lane >> 4) & 1) * 8;
    const uint32_t bRowL = (uint32_t)((lane & 7) + ((lane >> 4) & 1) * 8);
    const uint32_t bKof  = ((lane >> 3) & 1) * 8;

    // X: 2 threads per row; warp w owns rows [16w, 16w+16)
    const int srow = tid >> 1, half = tid & 1;
    const int srowc = min(srow, nrows - 1);
    const float* xrow = X + (size_t)g_perm[off + tile * ROWS + srowc] * DIM + half * 32;

    float acc[8][4];
    #pragma unroll
    for (int i = 0; i < 8; i++)
        #pragma unroll
        for (int j = 0; j < 4; j++) acc[i][j] = 0.f;

    // preload X chunk 0 into regs
    float4 xr[8];
    #pragma unroll
    for (int v = 0; v < 8; v++) xr[v] = *(const float4*)(xrow + v * 4);

    // ============ stages 0..3: layer 1, K chunks ============
    for (int c = 0; c < 4; c++) {
        CP_WAIT0();
        __syncthreads();                      // W[c] visible; all warps past MMA c-1
        stageW(wbuf[(c + 1) & 1], gwE + (c + 1) * 8192, tid, 64);
        CP_COMMIT();
        // convert X regs -> H planes (own rows)
        #pragma unroll
        for (int v = 0; v < 8; v++) {
            int k0 = half * 32 + v * 4;
            uint32_t o = (uint32_t)(srow * HPAD + k0) * 2;
            *(uint2*)(smem + SH_HI + o) = make_uint2(bf2(xr[v].x, xr[v].y), bf2(xr[v].z, xr[v].w));
            *(uint2*)(smem + SH_LO + o) =
                make_uint2(bf2(bfr(xr[v].x), bfr(xr[v].y)), bf2(bfr(xr[v].z), bfr(xr[v].w)));
        }
        if (c < 3) {
            #pragma unroll
            for (int v = 0; v < 8; v++) xr[v] = *(const float4*)(xrow + (c + 1) * 64 + v * 4);
        }
        __syncwarp();
        MMA_LAYER(acc, shi, slo, wbuf[c & 1]);
    }

    // ============ stages 4..7: layers 2..5 ============
    const int erow = rbase + (lane >> 2);
    for (int s = 4; s < 8; s++) {
        CP_WAIT0();
        __syncthreads();
        stageW(wbuf[(s + 1) & 1], gwE + (s + 1) * 8192, tid, (s == 7) ? 32 : 64);
        CP_COMMIT();
        // epilogue of previous layer -> H (own rows)
        const float* bb = sB + (s - 4) * 64;
        #pragma unroll
        for (int nt = 0; nt < 8; nt++) {
            int c0 = nt * 8 + (lane & 3) * 2;
            float b0v = bb[c0], b1v = bb[c0 + 1];
            float v0 = fmaxf(acc[nt][0] + b0v, 0.f);
            float v1 = fmaxf(acc[nt][1] + b1v, 0.f);
            float v2 = fmaxf(acc[nt][2] + b0v, 0.f);
            float v3 = fmaxf(acc[nt][3] + b1v, 0.f);
            uint32_t o0 = (uint32_t)(erow * HPAD + c0) * 2;
            uint32_t o1 = (uint32_t)((erow + 8) * HPAD + c0) * 2;
            *(uint32_t*)(smem + SH_HI + o0) = bf2(v0, v1);
            *(uint32_t*)(smem + SH_HI + o1) = bf2(v2, v3);
            *(uint32_t*)(smem + SH_LO + o0) = bf2(bfr(v0), bfr(v1));
            *(uint32_t*)(smem + SH_LO + o1) = bf2(bfr(v2), bfr(v3));
        }
        __syncwarp();
        #pragma unroll
        for (int i = 0; i < 8; i++)
            #pragma unroll
            for (int j = 0; j < 4; j++) acc[i][j] = 0.f;
        MMA_LAYER(acc, shi, slo, wbuf[s & 1]);
    }

    // ============ stage 8: layer 6 ============
    CP_WAIT0();
    __syncthreads();
    {   // epilogue of layer 5 -> H
        const float* bb = sB + 256;
        #pragma unroll
        for (int nt = 0; nt < 8; nt++) {
            int c0 = nt * 8 + (lane & 3) * 2;
            float b0v = bb[c0], b1v = bb[c0 + 1];
            float v0 = fmaxf(acc[nt][0] + b0v, 0.f);
            float v1 = fmaxf(acc[nt][1] + b1v, 0.f);
            float v2 = fmaxf(acc[nt][2] + b0v, 0.f);
            float v3 = fmaxf(acc[nt][3] + b1v, 0.f);
            uint32_t o0 = (uint32_t)(erow * HPAD + c0) * 2;
            uint32_t o1 = (uint32_t)((erow + 8) * HPAD + c0) * 2;
            *(uint32_t*)(smem + SH_HI + o0) = bf2(v0, v1);
            *(uint32_t*)(smem + SH_HI + o1) = bf2(v2, v3);
            *(uint32_t*)(smem + SH_LO + o0) = bf2(bfr(v0), bfr(v1));
            *(uint32_t*)(smem + SH_LO + o1) = bf2(bfr(v2), bfr(v3));
        }
    }
    __syncwarp();

    float acc6[3][4];
    #pragma unroll
    for (int i = 0; i < 3; i++)
        #pragma unroll
        for (int j = 0; j < 4; j++) acc6[i][j] = 0.f;

    {
        const uint32_t wb_ = wbuf[0];   // stage 8 buffer (8 & 1 == 0)
        #pragma unroll
        for (int ks = 0; ks < 4; ks++) {
            uint32_t k0 = ks * 16;
            uint32_t aoff = (aRow * HPAD + k0 + aKof) * 2;
            uint32_t ahi[4], alo[4];
            LDSM4(ahi, shi + aoff);
            LDSM4(alo, slo + aoff);
            #pragma unroll
            for (int p = 0; p < 2; p++) {
                uint32_t boff = ((p * 16 + bRowL) * HPAD + k0 + bKof) * 2;
                uint32_t bh[4], bl[4];
                LDSM4(bh, wb_ + boff);
                LDSM4(bl, wb_ + 9216 + boff);
                MMA(acc6[2 * p],     ahi, bh[0], bh[1]);
                MMA(acc6[2 * p],     ahi, bl[0], bl[1]);
                MMA(acc6[2 * p],     alo, bh[0], bh[1]);
                if (p == 0) {
                    MMA(acc6[1], ahi, bh[2], bh[3]);
                    MMA(acc6[1], ahi, bl[2], bl[3]);
                    MMA(acc6[1], alo, bh[2], bh[3]);
                }
            }
        }
    }

    // output scatter
    const int r0 = erow, r1 = erow + 8;
    int pr0 = (r0 < nrows) ? g_perm[off + tile * ROWS + r0] : -1;
    int pr1 = (r1 < nrows) ? g_perm[off + tile * ROWS + r1] : -1;
    const float* b6b = sB + 320;
    #pragma unroll
    for (int nt = 0; nt < 3; nt++) {
        int c0 = nt * 8 + (lane & 3) * 2;
        if (c0 + 1 < ACT) {
            float b0v = b6b[c0], b1v = b6b[c0 + 1];
            if (pr0 >= 0) {
                out[(size_t)pr0 * ACT + c0]     = acc6[nt][0] + b0v;
                out[(size_t)pr0 * ACT + c0 + 1] = acc6[nt][1] + b1v;
            }
            if (pr1 >= 0) {
                out[(size_t)pr1 * ACT + c0]     = acc6[nt][2] + b0v;
                out[(size_t)pr1 * ACT + c0 + 1] = acc6[nt][3] + b1v;
            }
        }
    }
}

extern "C" void kernel_launch(void* const* d_in, const int* in_sizes, int n_in,
                              void* d_out, int out_size) {
    const float* X  = (const float*)d_in[0];
    const int*   rm = (const int*)d_in[1];
    const float* W1 = (const float*)d_in[2];  const float* b1 = (const float*)d_in[3];
    const float* W2 = (const float*)d_in[4];  const float* b2 = (const float*)d_in[5];
    const float* W3 = (const float*)d_in[6];  const float* b3 = (const float*)d_in[7];
    const float* W4 = (const float*)d_in[8];  const float* b4 = (const float*)d_in[9];
    const float* W5 = (const float*)d_in[10]; const float* b5 = (const float*)d_in[11];
    const float* W6 = (const float*)d_in[12]; const float* b6 = (const float*)d_in[13];
    float* out = (float*)d_out;

    cudaFuncSetAttribute(k_moe, cudaFuncAttributeMaxDynamicSharedMemorySize, SMEM_TOTAL);

    k_pre1<<<HB + WB, 256>>>((const int4*)rm, W1, W2, W3, W4, W5, W6);
    k_pre2<<<1, 32>>>();
    k_scatter<<<HB, 256>>>((const int4*)rm);

    dim3 grid(NB / ROWS, NEXP);
    k_moe<<<grid, NTHR, SMEM_TOTAL>>>(X, b1, b2, b3, b4, b5, b6, out);
}

// round 7
// speedup vs baseline: 1.4002x; 1.4002x over previous
#include <cuda_runtime.h>
#include <cuda_bf16.h>
#include <cstdint>

#define NB    65536
#define DIM   256
#define HID   64
#define ACT   18
#define NEXP  8
#define ROWS  64
#define NTHR  128
#define HPAD  72        // halves per row stride (144B) -> conflict-free ldmatrix

// smem byte offsets (W double buffer + bias only; no activation smem)
#define SWSZ   18432        // one W buffer: hi 9216 + lo 9216
#define SBIAS  (2 * SWSZ)   // 36864; 352 floats
#define SMEM_TOTAL (SBIAS + 1408)

// ---------------- scratch ----------------
#define HB 64
__device__ int g_part[HB * NEXP];
__device__ int g_base[HB * NEXP];
__device__ int g_offsets[NEXP + 1];
__device__ int g_perm[NB];
// preconverted weights: per expert 9 slots (W1 c0..c3, W2..W5, W6) of 8192 bf16:
// hi plane [0,4096), lo plane [4096,8192); layout [n][64 k]
__device__ __align__(16) __nv_bfloat16 g_w[NEXP * 9 * 8192];

#define WCONV_TOTAL (NEXP * 34816)
#define WB ((WCONV_TOTAL + 1023) / 1024)

// ---------------- fused hist + wconv ----------------
__global__ void k_pre1(const int4* __restrict__ rm,
                       const float* __restrict__ W1, const float* __restrict__ W2,
                       const float* __restrict__ W3, const float* __restrict__ W4,
                       const float* __restrict__ W5, const float* __restrict__ W6) {
    int b = blockIdx.x, t = threadIdx.x;
    if (b < HB) {
        __shared__ int s_cnt[NEXP];
        if (t < NEXP) s_cnt[t] = 0;
        __syncthreads();
        int4 v = rm[b * 256 + t];
        int vv[4] = { v.x, v.y, v.z, v.w };
        #pragma unroll
        for (int r = 0; r < 4; r++) {
            unsigned m = __match_any_sync(0xffffffffu, vv[r]);
            if ((t & 31) == __ffs(m) - 1) atomicAdd(&s_cnt[vv[r]], __popc(m));
        }
        __syncthreads();
        if (t < NEXP) g_part[b * NEXP + t] = s_cnt[t];
    } else {
        int wb = b - HB;
        #pragma unroll
        for (int j = 0; j < 4; j++) {
            int idx = wb * 1024 + j * 256 + t;
            if (idx >= WCONV_TOTAL) break;
            int e = idx / 34816, r = idx % 34816;
            float w;
            int dst;
            if (r < 16384) {
                int c = r >> 12, nk = r & 4095, n = nk >> 6, k = nk & 63;
                w = W1[((size_t)e * 256 + c * 64 + k) * 64 + n];
                dst = (e * 9 + c) * 8192 + nk;
            } else if (r < 32768) {
                int l = (r - 16384) >> 12, nk = (r - 16384) & 4095, n = nk >> 6, k = nk & 63;
                const float* Wl = (l == 0) ? W2 : (l == 1) ? W3 : (l == 2) ? W4 : W5;
                w = Wl[((size_t)e * 64 + k) * 64 + n];
                dst = (e * 9 + 4 + l) * 8192 + nk;
            } else {
                int nk = r - 32768, n = nk >> 6, k = nk & 63;
                w = (n < ACT) ? W6[((size_t)e * 64 + k) * ACT + n] : 0.f;
                dst = (e * 9 + 8) * 8192 + nk;
            }
            __nv_bfloat16 h = __float2bfloat16(w);
            g_w[dst] = h;
            g_w[dst + 4096] = __float2bfloat16(w - __bfloat162float(h));
        }
    }
}

__global__ void k_pre2() {
    __shared__ int cnts[NEXP];
    int t = threadIdx.x;
    if (t < NEXP) {
        int run = 0;
        for (int b = 0; b < HB; b++) run += g_part[b * NEXP + t];
        cnts[t] = run;
    }
    __syncthreads();
    if (t == 0) {
        int off = 0;
        for (int e = 0; e < NEXP; e++) { g_offsets[e] = off; off += cnts[e]; }
        g_offsets[NEXP] = off;
    }
    __syncthreads();
    if (t < NEXP) {
        int run = g_offsets[t];
        for (int b = 0; b < HB; b++) {
            g_base[b * NEXP + t] = run;
            run += g_part[b * NEXP + t];
        }
    }
}

__global__ void k_scatter(const int4* __restrict__ rm) {
    __shared__ int s_cnt[NEXP];
    int b = blockIdx.x, t = threadIdx.x;
    if (t < NEXP) s_cnt[t] = 0;
    __syncthreads();
    int4 v = rm[b * 256 + t];
    int vv[4] = { v.x, v.y, v.z, v.w };
    unsigned lt = (1u << (t & 31)) - 1u;
    int i4 = (b * 256 + t) * 4;
    #pragma unroll
    for (int r = 0; r < 4; r++) {
        unsigned m = __match_any_sync(0xffffffffu, vv[r]);
        int leader = __ffs(m) - 1;
        int base = 0;
        if ((t & 31) == leader) base = atomicAdd(&s_cnt[vv[r]], __popc(m));
        base = __shfl_sync(0xffffffffu, base, leader);
        g_perm[g_base[b * NEXP + vv[r]] + base + __popc(m & lt)] = i4 + r;
    }
}

// ---------------- helpers ----------------
__device__ __forceinline__ uint32_t smem_u32(const void* p) {
    uint32_t a;
    asm("{ .reg .u64 t; cvta.to.shared.u64 t, %1; cvt.u32.u64 %0, t; }" : "=r"(a) : "l"(p));
    return a;
}
__device__ __forceinline__ uint32_t bf2(float a, float b) {
    uint32_t r;
    asm("cvt.rn.bf16x2.f32 %0, %1, %2;" : "=r"(r) : "f"(b), "f"(a));
    return r;
}
__device__ __forceinline__ float bfr(float x) {
    __nv_bfloat16 h = __float2bfloat16(x);
    return x - __bfloat162float(h);
}
#define CP16(dst, src) \
    asm volatile("cp.async.ca.shared.global [%0], [%1], 16;" :: "r"(dst), "l"(src))
#define CP_COMMIT() asm volatile("cp.async.commit_group;" ::: "memory")
#define CP_WAIT0()  asm volatile("cp.async.wait_group 0;" ::: "memory")

#define LDSM4(d, addr) \
    asm volatile("ldmatrix.sync.aligned.m8n8.x4.shared.b16 {%0,%1,%2,%3}, [%4];" \
        : "=r"((d)[0]), "=r"((d)[1]), "=r"((d)[2]), "=r"((d)[3]) : "r"(addr))

#define MMA(c, a, b0, b1) \
    asm volatile("mma.sync.aligned.m16n8k16.row.col.f32.bf16.bf16.f32 " \
        "{%0,%1,%2,%3},{%4,%5,%6,%7},{%8,%9},{%0,%1,%2,%3};" \
        : "+f"((c)[0]), "+f"((c)[1]), "+f"((c)[2]), "+f"((c)[3]) \
        : "r"((a)[0]), "r"((a)[1]), "r"((a)[2]), "r"((a)[3]), "r"(b0), "r"(b1))

// stage one weight slot (hi+lo planes) via cp.async; nW rows
__device__ __forceinline__ void stageW(uint32_t swb, const __nv_bfloat16* gw,
                                       int tid, int nW) {
    const char* src = (const char*)gw;
    int total = nW * 8;
    #pragma unroll 4
    for (int i = tid; i < total; i += NTHR) {
        int n = i >> 3, j = i & 7;
        uint32_t d = n * (HPAD * 2) + j * 16;
        int s = (n * 64 + j * 8) * 2;
        CP16(swb + d, src + s);
        CP16(swb + 9216 + d, src + 8192 + s);
    }
}

// MMA over one K=64 with A fragments in registers (fa/fl: [ktile][4])
#define MMA_REG(accv, fh, fl, wb_) do {                                        \
    _Pragma("unroll")                                                          \
    for (int ks = 0; ks < 4; ks++) {                                           \
        uint32_t k0 = ks * 16;                                                 \
        _Pragma("unroll")                                                      \
        for (int p = 0; p < 4; p++) {                                          \
            uint32_t boff = ((p * 16 + bRowL) * HPAD + k0 + bKof) * 2;         \
            uint32_t bh[4], bl[4];                                             \
            LDSM4(bh, (wb_) + boff);                                           \
            LDSM4(bl, (wb_) + 9216 + boff);                                    \
            MMA(accv[2 * p],     fh[ks], bh[0], bh[1]);                        \
            MMA(accv[2 * p],     fh[ks], bl[0], bl[1]);                        \
            MMA(accv[2 * p],     fl[ks], bh[0], bh[1]);                        \
            MMA(accv[2 * p + 1], fh[ks], bh[2], bh[3]);                        \
            MMA(accv[2 * p + 1], fh[ks], bl[2], bl[3]);                        \
            MMA(accv[2 * p + 1], fl[ks], bh[2], bh[3]);                        \
        }                                                                      \
    }                                                                          \
} while (0)

// ---------------- fused MoE (register-resident activations) ----------------
__global__ void __launch_bounds__(NTHR, 4) k_moe(
    const float* __restrict__ X,
    const float* __restrict__ b1, const float* __restrict__ b2,
    const float* __restrict__ b3, const float* __restrict__ b4,
    const float* __restrict__ b5, const float* __restrict__ b6,
    float* __restrict__ out)
{
    extern __shared__ char smem[];
    const int tid = threadIdx.x, wid = tid >> 5, lane = tid & 31;
    const int e = blockIdx.y, tile = blockIdx.x;
    const int off = g_offsets[e];
    const int cnt = g_offsets[e + 1] - off;
    if (tile * ROWS >= cnt) return;
    const int nrows = min(ROWS, cnt - tile * ROWS);

    const uint32_t sb = smem_u32(smem);
    const uint32_t wbuf[2] = { sb, sb + SWSZ };
    float* sB = (float*)(smem + SBIAS);

    const __nv_bfloat16* gwE = g_w + (size_t)e * 9 * 8192;

    // prologue: prefetch W slot 0
    stageW(wbuf[0], gwE, tid, 64);
    CP_COMMIT();

    if (tid < 64) {
        sB[tid]       = b1[e * HID + tid];
        sB[64 + tid]  = b2[e * HID + tid];
        sB[128 + tid] = b3[e * HID + tid];
        sB[192 + tid] = b4[e * HID + tid];
        sB[256 + tid] = b5[e * HID + tid];
    }
    if (tid < 32) sB[320 + tid] = (tid < ACT) ? b6[e * ACT + tid] : 0.f;

    const int rbase = wid * 16;
    const uint32_t bRowL = (uint32_t)((lane & 7) + ((lane >> 4) & 1) * 8);
    const uint32_t bKof  = ((lane >> 3) & 1) * 8;

    // this thread's two rows (r and r+8 of the warp tile)
    const int erow = rbase + (lane >> 2);
    const int r1i  = erow + 8;
    const int pr0  = (erow < nrows) ? g_perm[off + tile * ROWS + erow] : -1;
    const int pr1  = (r1i  < nrows) ? g_perm[off + tile * ROWS + r1i]  : -1;
    const float* xr0 = X + (size_t)((pr0 >= 0) ? pr0 : g_perm[off]) * DIM;
    const float* xr1 = X + (size_t)((pr1 >= 0) ? pr1 : g_perm[off]) * DIM;
    const int cofL = (lane & 3) * 2;          // col pair offset low
    const int cofH = 8 + cofL;                // high half of k-tile

    float acc[8][4];
    #pragma unroll
    for (int i = 0; i < 8; i++)
        #pragma unroll
        for (int j = 0; j < 4; j++) acc[i][j] = 0.f;

    // X fragment source values for current chunk: xf[kt][0]=r/klo 1=r8/klo 2=r/khi 3=r8/khi
    float2 xf[4][4];
    #pragma unroll
    for (int kt = 0; kt < 4; kt++) {
        int kb = kt * 16;
        xf[kt][0] = *(const float2*)(xr0 + kb + cofL);
        xf[kt][1] = *(const float2*)(xr1 + kb + cofL);
        xf[kt][2] = *(const float2*)(xr0 + kb + cofH);
        xf[kt][3] = *(const float2*)(xr1 + kb + cofH);
    }

    // ============ layer 1: 4 chunks of K=64 ============
    for (int c = 0; c < 4; c++) {
        CP_WAIT0();
        __syncthreads();                       // W[c] ready; all warps past MMA c-1
        stageW(wbuf[(c + 1) & 1], gwE + (c + 1) * 8192, tid, 64);
        CP_COMMIT();
        const uint32_t wb_ = wbuf[c & 1];
        #pragma unroll
        for (int ks = 0; ks < 4; ks++) {
            uint32_t fh[1][4], fl[1][4];
            #pragma unroll
            for (int q = 0; q < 4; q++) {
                float2 d = xf[ks][q];
                fh[0][q] = bf2(d.x, d.y);
                fl[0][q] = bf2(bfr(d.x), bfr(d.y));
            }
            if (c < 3) {                       // prefetch next chunk, same ktile slot
                int kb = (c + 1) * 64 + ks * 16;
                xf[ks][0] = *(const float2*)(xr0 + kb + cofL);
                xf[ks][1] = *(const float2*)(xr1 + kb + cofL);
                xf[ks][2] = *(const float2*)(xr0 + kb + cofH);
                xf[ks][3] = *(const float2*)(xr1 + kb + cofH);
            }
            uint32_t k0 = ks * 16;
            #pragma unroll
            for (int p = 0; p < 4; p++) {
                uint32_t boff = ((p * 16 + bRowL) * HPAD + k0 + bKof) * 2;
                uint32_t bh[4], bl[4];
                LDSM4(bh, wb_ + boff);
                LDSM4(bl, wb_ + 9216 + boff);
                MMA(acc[2 * p],     fh[0], bh[0], bh[1]);
                MMA(acc[2 * p],     fh[0], bl[0], bl[1]);
                MMA(acc[2 * p],     fl[0], bh[0], bh[1]);
                MMA(acc[2 * p + 1], fh[0], bh[2], bh[3]);
                MMA(acc[2 * p + 1], fh[0], bl[2], bl[3]);
                MMA(acc[2 * p + 1], fl[0], bh[2], bh[3]);
            }
        }
    }

    // ============ layers 2..5 (stages 4..7) ============
    for (int s = 4; s < 8; s++) {
        CP_WAIT0();
        __syncthreads();
        stageW(wbuf[(s + 1) & 1], gwE + (s + 1) * 8192, tid, (s == 7) ? 32 : 64);
        CP_COMMIT();
        // epilogue of prev layer -> A fragments in registers
        const float* bb = sB + (s - 4) * 64;
        uint32_t fh[4][4], fl[4][4];
        #pragma unroll
        for (int kt = 0; kt < 4; kt++) {
            #pragma unroll
            for (int h = 0; h < 2; h++) {      // h=0: k low (nt=2kt), h=1: k high (nt=2kt+1)
                int nt = 2 * kt + h;
                float b0v = bb[nt * 8 + cofL], b1v = bb[nt * 8 + cofL + 1];
                float v0 = fmaxf(acc[nt][0] + b0v, 0.f);
                float v1 = fmaxf(acc[nt][1] + b1v, 0.f);
                float v2 = fmaxf(acc[nt][2] + b0v, 0.f);
                float v3 = fmaxf(acc[nt][3] + b1v, 0.f);
                fh[kt][2 * h]     = bf2(v0, v1);
                fh[kt][2 * h + 1] = bf2(v2, v3);
                fl[kt][2 * h]     = bf2(bfr(v0), bfr(v1));
                fl[kt][2 * h + 1] = bf2(bfr(v2), bfr(v3));
            }
        }
        #pragma unroll
        for (int i = 0; i < 8; i++)
            #pragma unroll
            for (int j = 0; j < 4; j++) acc[i][j] = 0.f;
        MMA_REG(acc, fh, fl, wbuf[s & 1]);
    }

    // ============ layer 6 (stage 8) ============
    CP_WAIT0();
    __syncthreads();
    {
        const float* bb = sB + 256;
        uint32_t fh[4][4], fl[4][4];
        #pragma unroll
        for (int kt = 0; kt < 4; kt++) {
            #pragma unroll
            for (int h = 0; h < 2; h++) {
                int nt = 2 * kt + h;
                float b0v = bb[nt * 8 + cofL], b1v = bb[nt * 8 + cofL + 1];
                float v0 = fmaxf(acc[nt][0] + b0v, 0.f);
                float v1 = fmaxf(acc[nt][1] + b1v, 0.f);
                float v2 = fmaxf(acc[nt][2] + b0v, 0.f);
                float v3 = fmaxf(acc[nt][3] + b1v, 0.f);
                fh[kt][2 * h]     = bf2(v0, v1);
                fh[kt][2 * h + 1] = bf2(v2, v3);
                fl[kt][2 * h]     = bf2(bfr(v0), bfr(v1));
                fl[kt][2 * h + 1] = bf2(bfr(v2), bfr(v3));
            }
        }
        float acc6[3][4];
        #pragma unroll
        for (int i = 0; i < 3; i++)
            #pragma unroll
            for (int j = 0; j < 4; j++) acc6[i][j] = 0.f;

        const uint32_t wb_ = wbuf[0];          // slot 8 landed in buf0
        #pragma unroll
        for (int ks = 0; ks < 4; ks++) {
            uint32_t k0 = ks * 16;
            #pragma unroll
            for (int p = 0; p < 2; p++) {
                uint32_t boff = ((p * 16 + bRowL) * HPAD + k0 + bKof) * 2;
                uint32_t bh[4], bl[4];
                LDSM4(bh, wb_ + boff);
                LDSM4(bl, wb_ + 9216 + boff);
                MMA(acc6[2 * p],     fh[ks], bh[0], bh[1]);
                MMA(acc6[2 * p],     fh[ks], bl[0], bl[1]);
                MMA(acc6[2 * p],     fl[ks], bh[0], bh[1]);
                if (p == 0) {
                    MMA(acc6[1], fh[ks], bh[2], bh[3]);
                    MMA(acc6[1], fh[ks], bl[2], bl[3]);
                    MMA(acc6[1], fl[ks], bh[2], bh[3]);
                }
            }
        }

        const float* b6b = sB + 320;
        #pragma unroll
        for (int nt = 0; nt < 3; nt++) {
            int c0 = nt * 8 + cofL;
            if (c0 + 1 < ACT) {
                float b0v = b6b[c0], b1v = b6b[c0 + 1];
                if (pr0 >= 0) {
                    out[(size_t)pr0 * ACT + c0]     = acc6[nt][0] + b0v;
                    out[(size_t)pr0 * ACT + c0 + 1] = acc6[nt][1] + b1v;
                }
                if (pr1 >= 0) {
                    out[(size_t)pr1 * ACT + c0]     = acc6[nt][2] + b0v;
                    out[(size_t)pr1 * ACT + c0 + 1] = acc6[nt][3] + b1v;
                }
            }
        }
    }
}

extern "C" void kernel_launch(void* const* d_in, const int* in_sizes, int n_in,
                              void* d_out, int out_size) {
    const float* X  = (const float*)d_in[0];
    const int*   rm = (const int*)d_in[1];
    const float* W1 = (const float*)d_in[2];  const float* b1 = (const float*)d_in[3];
    const float* W2 = (const float*)d_in[4];  const float* b2 = (const float*)d_in[5];
    const float* W3 = (const float*)d_in[6];  const float* b3 = (const float*)d_in[7];
    const float* W4 = (const float*)d_in[8];  const float* b4 = (const float*)d_in[9];
    const float* W5 = (const float*)d_in[10]; const float* b5 = (const float*)d_in[11];
    const float* W6 = (const float*)d_in[12]; const float* b6 = (const float*)d_in[13];
    float* out = (float*)d_out;

    cudaFuncSetAttribute(k_moe, cudaFuncAttributeMaxDynamicSharedMemorySize, SMEM_TOTAL);

    k_pre1<<<HB + WB, 256>>>((const int4*)rm, W1, W2, W3, W4, W5, W6);
    k_pre2<<<1, 32>>>();
    k_scatter<<<HB, 256>>>((const int4*)rm);

    dim3 grid(NB / ROWS, NEXP);
    k_moe<<<grid, NTHR, SMEM_TOTAL>>>(X, b1, b2, b3, b4, b5, b6, out);
}

// round 8
// speedup vs baseline: 1.4224x; 1.0159x over previous
#include <cuda_runtime.h>
#include <cuda_bf16.h>
#include <cstdint>

#define NB    65536
#define DIM   256
#define HID   64
#define ACT   18
#define NEXP  8
#define ROWS  128
#define NTHR  128
#define HPAD  72        // halves per row stride (144B) -> conflict-free ldmatrix

// smem: W double buffer + bias
#define SWSZ   18432
#define SBIAS  (2 * SWSZ)
#define SMEM_TOTAL (SBIAS + 1408)

// ---------------- scratch ----------------
#define HB 64
__device__ int g_part[HB * NEXP];
__device__ int g_base[HB * NEXP];
__device__ int g_offsets[NEXP + 1];
__device__ int g_perm[NB];
__device__ __align__(16) __nv_bfloat16 g_w[NEXP * 9 * 8192];

#define WCONV_TOTAL (NEXP * 34816)
#define WB ((WCONV_TOTAL + 1023) / 1024)

// ---------------- fused hist + wconv ----------------
__global__ void k_pre1(const int4* __restrict__ rm,
                       const float* __restrict__ W1, const float* __restrict__ W2,
                       const float* __restrict__ W3, const float* __restrict__ W4,
                       const float* __restrict__ W5, const float* __restrict__ W6) {
    int b = blockIdx.x, t = threadIdx.x;
    if (b < HB) {
        __shared__ int s_cnt[NEXP];
        if (t < NEXP) s_cnt[t] = 0;
        __syncthreads();
        int4 v = rm[b * 256 + t];
        int vv[4] = { v.x, v.y, v.z, v.w };
        #pragma unroll
        for (int r = 0; r < 4; r++) {
            unsigned m = __match_any_sync(0xffffffffu, vv[r]);
            if ((t & 31) == __ffs(m) - 1) atomicAdd(&s_cnt[vv[r]], __popc(m));
        }
        __syncthreads();
        if (t < NEXP) g_part[b * NEXP + t] = s_cnt[t];
    } else {
        int wb = b - HB;
        #pragma unroll
        for (int j = 0; j < 4; j++) {
            int idx = wb * 1024 + j * 256 + t;
            if (idx >= WCONV_TOTAL) break;
            int e = idx / 34816, r = idx % 34816;
            float w;
            int dst;
            if (r < 16384) {
                int c = r >> 12, nk = r & 4095, n = nk >> 6, k = nk & 63;
                w = W1[((size_t)e * 256 + c * 64 + k) * 64 + n];
                dst = (e * 9 + c) * 8192 + nk;
            } else if (r < 32768) {
                int l = (r - 16384) >> 12, nk = (r - 16384) & 4095, n = nk >> 6, k = nk & 63;
                const float* Wl = (l == 0) ? W2 : (l == 1) ? W3 : (l == 2) ? W4 : W5;
                w = Wl[((size_t)e * 64 + k) * 64 + n];
                dst = (e * 9 + 4 + l) * 8192 + nk;
            } else {
                int nk = r - 32768, n = nk >> 6, k = nk & 63;
                w = (n < ACT) ? W6[((size_t)e * 64 + k) * ACT + n] : 0.f;
                dst = (e * 9 + 8) * 8192 + nk;
            }
            __nv_bfloat16 h = __float2bfloat16(w);
            g_w[dst] = h;
            g_w[dst + 4096] = __float2bfloat16(w - __bfloat162float(h));
        }
    }
}

__global__ void k_pre2() {
    __shared__ int cnts[NEXP];
    int t = threadIdx.x;
    if (t < NEXP) {
        int run = 0;
        for (int b = 0; b < HB; b++) run += g_part[b * NEXP + t];
        cnts[t] = run;
    }
    __syncthreads();
    if (t == 0) {
        int off = 0;
        for (int e = 0; e < NEXP; e++) { g_offsets[e] = off; off += cnts[e]; }
        g_offsets[NEXP] = off;
    }
    __syncthreads();
    if (t < NEXP) {
        int run = g_offsets[t];
        for (int b = 0; b < HB; b++) {
            g_base[b * NEXP + t] = run;
            run += g_part[b * NEXP + t];
        }
    }
}

__global__ void k_scatter(const int4* __restrict__ rm) {
    __shared__ int s_cnt[NEXP];
    int b = blockIdx.x, t = threadIdx.x;
    if (t < NEXP) s_cnt[t] = 0;
    __syncthreads();
    int4 v = rm[b * 256 + t];
    int vv[4] = { v.x, v.y, v.z, v.w };
    unsigned lt = (1u << (t & 31)) - 1u;
    int i4 = (b * 256 + t) * 4;
    #pragma unroll
    for (int r = 0; r < 4; r++) {
        unsigned m = __match_any_sync(0xffffffffu, vv[r]);
        int leader = __ffs(m) - 1;
        int base = 0;
        if ((t & 31) == leader) base = atomicAdd(&s_cnt[vv[r]], __popc(m));
        base = __shfl_sync(0xffffffffu, base, leader);
        g_perm[g_base[b * NEXP + vv[r]] + base + __popc(m & lt)] = i4 + r;
    }
}

// ---------------- helpers ----------------
__device__ __forceinline__ uint32_t smem_u32(const void* p) {
    uint32_t a;
    asm("{ .reg .u64 t; cvta.to.shared.u64 t, %1; cvt.u32.u64 %0, t; }" : "=r"(a) : "l"(p));
    return a;
}
__device__ __forceinline__ uint32_t bf2(float a, float b) {
    uint32_t r;
    asm("cvt.rn.bf16x2.f32 %0, %1, %2;" : "=r"(r) : "f"(b), "f"(a));
    return r;
}
__device__ __forceinline__ float bfr(float x) {
    __nv_bfloat16 h = __float2bfloat16(x);
    return x - __bfloat162float(h);
}
#define CP16(dst, src) \
    asm volatile("cp.async.ca.shared.global [%0], [%1], 16;" :: "r"(dst), "l"(src))
#define CP_COMMIT() asm volatile("cp.async.commit_group;" ::: "memory")
#define CP_WAIT0()  asm volatile("cp.async.wait_group 0;" ::: "memory")

#define LDSM4(d, addr) \
    asm volatile("ldmatrix.sync.aligned.m8n8.x4.shared.b16 {%0,%1,%2,%3}, [%4];" \
        : "=r"((d)[0]), "=r"((d)[1]), "=r"((d)[2]), "=r"((d)[3]) : "r"(addr))

#define MMA(c, a, b0, b1) \
    asm volatile("mma.sync.aligned.m16n8k16.row.col.f32.bf16.bf16.f32 " \
        "{%0,%1,%2,%3},{%4,%5,%6,%7},{%8,%9},{%0,%1,%2,%3};" \
        : "+f"((c)[0]), "+f"((c)[1]), "+f"((c)[2]), "+f"((c)[3]) \
        : "r"((a)[0]), "r"((a)[1]), "r"((a)[2]), "r"((a)[3]), "r"(b0), "r"(b1))

__device__ __forceinline__ void stageW(uint32_t swb, const __nv_bfloat16* gw,
                                       int tid, int nW) {
    const char* src = (const char*)gw;
    int total = nW * 8;
    #pragma unroll 4
    for (int i = tid; i < total; i += NTHR) {
        int n = i >> 3, j = i & 7;
        uint32_t d = n * (HPAD * 2) + j * 16;
        int s = (n * 64 + j * 8) * 2;
        CP16(swb + d, src + s);
        CP16(swb + 9216 + d, src + 8192 + s);
    }
}

// 6 MMAs of one row-block against loaded B frags
#define MMA6(accv, fh, fl, bh, bl) do {                  \
    MMA(accv[0], fh, (bh)[0], (bh)[1]);                  \
    MMA(accv[0], fh, (bl)[0], (bl)[1]);                  \
    MMA(accv[0], fl, (bh)[0], (bh)[1]);                  \
    MMA(accv[1], fh, (bh)[2], (bh)[3]);                  \
    MMA(accv[1], fh, (bl)[2], (bl)[3]);                  \
    MMA(accv[1], fl, (bh)[2], (bh)[3]);                  \
} while (0)

// ---------------- fused MoE (32 rows/warp, register activations) ----------------
__global__ void __launch_bounds__(NTHR, 3) k_moe(
    const float* __restrict__ X,
    const float* __restrict__ b1, const float* __restrict__ b2,
    const float* __restrict__ b3, const float* __restrict__ b4,
    const float* __restrict__ b5, const float* __restrict__ b6,
    float* __restrict__ out)
{
    extern __shared__ char smem[];
    const int tid = threadIdx.x, wid = tid >> 5, lane = tid & 31;
    const int e = blockIdx.y, tile = blockIdx.x;
    const int off = g_offsets[e];
    const int cnt = g_offsets[e + 1] - off;
    if (tile * ROWS >= cnt) return;
    const int nrows = min(ROWS, cnt - tile * ROWS);

    const uint32_t sb = smem_u32(smem);
    const uint32_t wbuf[2] = { sb, sb + SWSZ };
    float* sB = (float*)(smem + SBIAS);

    const __nv_bfloat16* gwE = g_w + (size_t)e * 9 * 8192;

    stageW(wbuf[0], gwE, tid, 64);
    CP_COMMIT();

    if (tid < 64) {
        sB[tid]       = b1[e * HID + tid];
        sB[64 + tid]  = b2[e * HID + tid];
        sB[128 + tid] = b3[e * HID + tid];
        sB[192 + tid] = b4[e * HID + tid];
        sB[256 + tid] = b5[e * HID + tid];
    }
    if (tid < 32) sB[320 + tid] = (tid < ACT) ? b6[e * ACT + tid] : 0.f;

    const uint32_t bRowL = (uint32_t)((lane & 7) + ((lane >> 4) & 1) * 8);
    const uint32_t bKof  = ((lane >> 3) & 1) * 8;

    // this thread's four rows: erow, +8, +16, +24 within warp tile of 32
    const int erow = wid * 32 + (lane >> 2);
    int pr[4];
    const float* xr[4];
    #pragma unroll
    for (int q = 0; q < 4; q++) {
        int rr = erow + q * 8;
        pr[q] = (rr < nrows) ? g_perm[off + tile * ROWS + rr] : -1;
        xr[q] = X + (size_t)((pr[q] >= 0) ? pr[q] : g_perm[off]) * DIM;
    }
    const int cofL = (lane & 3) * 2;
    const int cofH = 8 + cofL;

    float accA[8][4], accB[8][4];
    #pragma unroll
    for (int i = 0; i < 8; i++)
        #pragma unroll
        for (int j = 0; j < 4; j++) { accA[i][j] = 0.f; accB[i][j] = 0.f; }

    // current-ktile X values: [0]=r/L [1]=r8/L [2]=r/H [3]=r8/H [4..7] rows 16,24
    float2 cur[8];
    #pragma unroll
    for (int q = 0; q < 2; q++) {
        cur[4 * q + 0] = *(const float2*)(xr[2 * q + 0] + cofL);
        cur[4 * q + 1] = *(const float2*)(xr[2 * q + 1] + cofL);
        cur[4 * q + 2] = *(const float2*)(xr[2 * q + 0] + cofH);
        cur[4 * q + 3] = *(const float2*)(xr[2 * q + 1] + cofH);
    }

    // ============ layer 1: 4 chunks of K=64 ============
    for (int c = 0; c < 4; c++) {
        CP_WAIT0();
        __syncthreads();
        stageW(wbuf[(c + 1) & 1], gwE + (c + 1) * 8192, tid, 64);
        CP_COMMIT();
        const uint32_t wb_ = wbuf[c & 1];
        #pragma unroll
        for (int ks = 0; ks < 4; ks++) {
            uint32_t fhA[4], flA[4], fhB[4], flB[4];
            #pragma unroll
            for (int q = 0; q < 4; q++) {
                float2 dA = cur[q], dB = cur[4 + q];
                fhA[q] = bf2(dA.x, dA.y);
                flA[q] = bf2(bfr(dA.x), bfr(dA.y));
                fhB[q] = bf2(dB.x, dB.y);
                flB[q] = bf2(bfr(dB.x), bfr(dB.y));
            }
            if (!(c == 3 && ks == 3)) {        // prefetch next ktile
                int kb = c * 64 + (ks + 1) * 16;
                if (ks == 3) kb = (c + 1) * 64;
                #pragma unroll
                for (int q = 0; q < 2; q++) {
                    cur[4 * q + 0] = *(const float2*)(xr[2 * q + 0] + kb + cofL);
                    cur[4 * q + 1] = *(const float2*)(xr[2 * q + 1] + kb + cofL);
                    cur[4 * q + 2] = *(const float2*)(xr[2 * q + 0] + kb + cofH);
                    cur[4 * q + 3] = *(const float2*)(xr[2 * q + 1] + kb + cofH);
                }
            }
            uint32_t k0 = ks * 16;
            #pragma unroll
            for (int p = 0; p < 4; p++) {
                uint32_t boff = ((p * 16 + bRowL) * HPAD + k0 + bKof) * 2;
                uint32_t bh[4], bl[4];
                LDSM4(bh, wb_ + boff);
                LDSM4(bl, wb_ + 9216 + boff);
                MMA6((accA + 2 * p), fhA, flA, bh, bl);
                MMA6((accB + 2 * p), fhB, flB, bh, bl);
            }
        }
    }

    // ============ layers 2..5 (stages 4..7) ============
    for (int s = 4; s < 8; s++) {
        CP_WAIT0();
        __syncthreads();
        stageW(wbuf[(s + 1) & 1], gwE + (s + 1) * 8192, tid, (s == 7) ? 32 : 64);
        CP_COMMIT();
        const float* bb = sB + (s - 4) * 64;
        uint32_t fhA[4][4], flA[4][4], fhB[4][4], flB[4][4];
        #pragma unroll
        for (int kt = 0; kt < 4; kt++) {
            #pragma unroll
            for (int h = 0; h < 2; h++) {
                int nt = 2 * kt + h;
                float b0v = bb[nt * 8 + cofL], b1v = bb[nt * 8 + cofL + 1];
                float v0 = fmaxf(accA[nt][0] + b0v, 0.f);
                float v1 = fmaxf(accA[nt][1] + b1v, 0.f);
                float v2 = fmaxf(accA[nt][2] + b0v, 0.f);
                float v3 = fmaxf(accA[nt][3] + b1v, 0.f);
                fhA[kt][2 * h]     = bf2(v0, v1);
                fhA[kt][2 * h + 1] = bf2(v2, v3);
                flA[kt][2 * h]     = bf2(bfr(v0), bfr(v1));
                flA[kt][2 * h + 1] = bf2(bfr(v2), bfr(v3));
                float w0 = fmaxf(accB[nt][0] + b0v, 0.f);
                float w1 = fmaxf(accB[nt][1] + b1v, 0.f);
                float w2 = fmaxf(accB[nt][2] + b0v, 0.f);
                float w3 = fmaxf(accB[nt][3] + b1v, 0.f);
                fhB[kt][2 * h]     = bf2(w0, w1);
                fhB[kt][2 * h + 1] = bf2(w2, w3);
                flB[kt][2 * h]     = bf2(bfr(w0), bfr(w1));
                flB[kt][2 * h + 1] = bf2(bfr(w2), bfr(w3));
            }
        }
        #pragma unroll
        for (int i = 0; i < 8; i++)
            #pragma unroll
            for (int j = 0; j < 4; j++) { accA[i][j] = 0.f; accB[i][j] = 0.f; }
        #pragma unroll
        for (int ks = 0; ks < 4; ks++) {
            uint32_t k0 = ks * 16;
            #pragma unroll
            for (int p = 0; p < 4; p++) {
                uint32_t boff = ((p * 16 + bRowL) * HPAD + k0 + bKof) * 2;
                uint32_t bh[4], bl[4];
                LDSM4(bh, wbuf[s & 1] + boff);
                LDSM4(bl, wbuf[s & 1] + 9216 + boff);
                MMA6((accA + 2 * p), fhA[ks], flA[ks], bh, bl);
                MMA6((accB + 2 * p), fhB[ks], flB[ks], bh, bl);
            }
        }
    }

    // ============ layer 6 (stage 8) ============
    CP_WAIT0();
    __syncthreads();
    {
        const float* bb = sB + 256;
        uint32_t fhA[4][4], flA[4][4], fhB[4][4], flB[4][4];
        #pragma unroll
        for (int kt = 0; kt < 4; kt++) {
            #pragma unroll
            for (int h = 0; h < 2; h++) {
                int nt = 2 * kt + h;
                float b0v = bb[nt * 8 + cofL], b1v = bb[nt * 8 + cofL + 1];
                float v0 = fmaxf(accA[nt][0] + b0v, 0.f);
                float v1 = fmaxf(accA[nt][1] + b1v, 0.f);
                float v2 = fmaxf(accA[nt][2] + b0v, 0.f);
                float v3 = fmaxf(accA[nt][3] + b1v, 0.f);
                fhA[kt][2 * h]     = bf2(v0, v1);
                fhA[kt][2 * h + 1] = bf2(v2, v3);
                flA[kt][2 * h]     = bf2(bfr(v0), bfr(v1));
                flA[kt][2 * h + 1] = bf2(bfr(v2), bfr(v3));
                float w0 = fmaxf(accB[nt][0] + b0v, 0.f);
                float w1 = fmaxf(accB[nt][1] + b1v, 0.f);
                float w2 = fmaxf(accB[nt][2] + b0v, 0.f);
                float w3 = fmaxf(accB[nt][3] + b1v, 0.f);
                fhB[kt][2 * h]     = bf2(w0, w1);
                fhB[kt][2 * h + 1] = bf2(w2, w3);
                flB[kt][2 * h]     = bf2(bfr(w0), bfr(w1));
                flB[kt][2 * h + 1] = bf2(bfr(w2), bfr(w3));
            }
        }
        float acc6A[4][4], acc6B[4][4];
        #pragma unroll
        for (int i = 0; i < 4; i++)
            #pragma unroll
            for (int j = 0; j < 4; j++) { acc6A[i][j] = 0.f; acc6B[i][j] = 0.f; }

        const uint32_t wb_ = wbuf[0];
        #pragma unroll
        for (int ks = 0; ks < 4; ks++) {
            uint32_t k0 = ks * 16;
            #pragma unroll
            for (int p = 0; p < 2; p++) {
                uint32_t boff = ((p * 16 + bRowL) * HPAD + k0 + bKof) * 2;
                uint32_t bh[4], bl[4];
                LDSM4(bh, wb_ + boff);
                LDSM4(bl, wb_ + 9216 + boff);
                MMA6((acc6A + 2 * p), fhA[ks], flA[ks], bh, bl);
                MMA6((acc6B + 2 * p), fhB[ks], flB[ks], bh, bl);
            }
        }

        const float* b6b = sB + 320;
        #pragma unroll
        for (int nt = 0; nt < 3; nt++) {
            int c0 = nt * 8 + cofL;
            if (c0 + 1 < ACT) {
                float b0v = b6b[c0], b1v = b6b[c0 + 1];
                if (pr[0] >= 0) {
                    out[(size_t)pr[0] * ACT + c0]     = acc6A[nt][0] + b0v;
                    out[(size_t)pr[0] * ACT + c0 + 1] = acc6A[nt][1] + b1v;
                }
                if (pr[1] >= 0) {
                    out[(size_t)pr[1] * ACT + c0]     = acc6A[nt][2] + b0v;
                    out[(size_t)pr[1] * ACT + c0 + 1] = acc6A[nt][3] + b1v;
                }
                if (pr[2] >= 0) {
                    out[(size_t)pr[2] * ACT + c0]     = acc6B[nt][0] + b0v;
                    out[(size_t)pr[2] * ACT + c0 + 1] = acc6B[nt][1] + b1v;
                }
                if (pr[3] >= 0) {
                    out[(size_t)pr[3] * ACT + c0]     = acc6B[nt][2] + b0v;
                    out[(size_t)pr[3] * ACT + c0 + 1] = acc6B[nt][3] + b1v;
                }
            }
        }
    }
}

extern "C" void kernel_launch(void* const* d_in, const int* in_sizes, int n_in,
                              void* d_out, int out_size) {
    const float* X  = (const float*)d_in[0];
    const int*   rm = (const int*)d_in[1];
    const float* W1 = (const float*)d_in[2];  const float* b1 = (const float*)d_in[3];
    const float* W2 = (const float*)d_in[4];  const float* b2 = (const float*)d_in[5];
    const float* W3 = (const float*)d_in[6];  const float* b3 = (const float*)d_in[7];
    const float* W4 = (const float*)d_in[8];  const float* b4 = (const float*)d_in[9];
    const float* W5 = (const float*)d_in[10]; const float* b5 = (const float*)d_in[11];
    const float* W6 = (const float*)d_in[12]; const float* b6 = (const float*)d_in[13];
    float* out = (float*)d_out;

    cudaFuncSetAttribute(k_moe, cudaFuncAttributeMaxDynamicSharedMemorySize, SMEM_TOTAL);

    k_pre1<<<HB + WB, 256>>>((const int4*)rm, W1, W2, W3, W4, W5, W6);
    k_pre2<<<1, 32>>>();
    k_scatter<<<HB, 256>>>((const int4*)rm);

    dim3 grid(NB / ROWS, NEXP);
    k_moe<<<grid, NTHR, SMEM_TOTAL>>>(X, b1, b2, b3, b4, b5, b6, out);
}

// round 9
// speedup vs baseline: 1.4404x; 1.0126x over previous
#include <cuda_runtime.h>
#include <cuda_bf16.h>
#include <cstdint>

#define NB    65536
#define DIM   256
#define HID   64
#define ACT   18
#define NEXP  8
#define ROWS  128
#define NTHR  128
#define HPAD  72        // halves per row stride (144B) -> conflict-free ldmatrix

// smem: W double buffer + bias
#define SWSZ   18432
#define SBIAS  (2 * SWSZ)
#define SMEM_TOTAL (SBIAS + 1408)

// ---------------- scratch ----------------
#define HB 64
__device__ int g_part[HB * NEXP];
__device__ int g_base[HB * NEXP];
__device__ int g_offsets[NEXP + 1];
__device__ int g_perm[NB];
__device__ __align__(16) __nv_bfloat16 g_w[NEXP * 9 * 8192];

#define WCONV_TOTAL (NEXP * 34816)
#define WB ((WCONV_TOTAL + 1023) / 1024)

// ---------------- fused hist + wconv ----------------
__global__ void k_pre1(const int4* __restrict__ rm,
                       const float* __restrict__ W1, const float* __restrict__ W2,
                       const float* __restrict__ W3, const float* __restrict__ W4,
                       const float* __restrict__ W5, const float* __restrict__ W6) {
    int b = blockIdx.x, t = threadIdx.x;
    if (b < HB) {
        __shared__ int s_cnt[NEXP];
        if (t < NEXP) s_cnt[t] = 0;
        __syncthreads();
        int4 v = rm[b * 256 + t];
        int vv[4] = { v.x, v.y, v.z, v.w };
        #pragma unroll
        for (int r = 0; r < 4; r++) {
            unsigned m = __match_any_sync(0xffffffffu, vv[r]);
            if ((t & 31) == __ffs(m) - 1) atomicAdd(&s_cnt[vv[r]], __popc(m));
        }
        __syncthreads();
        if (t < NEXP) g_part[b * NEXP + t] = s_cnt[t];
    } else {
        int wb = b - HB;
        #pragma unroll
        for (int j = 0; j < 4; j++) {
            int idx = wb * 1024 + j * 256 + t;
            if (idx >= WCONV_TOTAL) break;
            int e = idx / 34816, r = idx % 34816;
            float w;
            int dst;
            if (r < 16384) {
                int c = r >> 12, nk = r & 4095, n = nk >> 6, k = nk & 63;
                w = W1[((size_t)e * 256 + c * 64 + k) * 64 + n];
                dst = (e * 9 + c) * 8192 + nk;
            } else if (r < 32768) {
                int l = (r - 16384) >> 12, nk = (r - 16384) & 4095, n = nk >> 6, k = nk & 63;
                const float* Wl = (l == 0) ? W2 : (l == 1) ? W3 : (l == 2) ? W4 : W5;
                w = Wl[((size_t)e * 64 + k) * 64 + n];
                dst = (e * 9 + 4 + l) * 8192 + nk;
            } else {
                int nk = r - 32768, n = nk >> 6, k = nk & 63;
                w = (n < ACT) ? W6[((size_t)e * 64 + k) * ACT + n] : 0.f;
                dst = (e * 9 + 8) * 8192 + nk;
            }
            __nv_bfloat16 h = __float2bfloat16(w);
            g_w[dst] = h;
            g_w[dst + 4096] = __float2bfloat16(w - __bfloat162float(h));
        }
    }
}

__global__ void k_pre2() {
    __shared__ int cnts[NEXP];
    int t = threadIdx.x;
    if (t < NEXP) {
        int run = 0;
        for (int b = 0; b < HB; b++) run += g_part[b * NEXP + t];
        cnts[t] = run;
    }
    __syncthreads();
    if (t == 0) {
        int off = 0;
        for (int e = 0; e < NEXP; e++) { g_offsets[e] = off; off += cnts[e]; }
        g_offsets[NEXP] = off;
    }
    __syncthreads();
    if (t < NEXP) {
        int run = g_offsets[t];
        for (int b = 0; b < HB; b++) {
            g_base[b * NEXP + t] = run;
            run += g_part[b * NEXP + t];
        }
    }
}

__global__ void k_scatter(const int4* __restrict__ rm) {
    __shared__ int s_cnt[NEXP];
    int b = blockIdx.x, t = threadIdx.x;
    if (t < NEXP) s_cnt[t] = 0;
    __syncthreads();
    int4 v = rm[b * 256 + t];
    int vv[4] = { v.x, v.y, v.z, v.w };
    unsigned lt = (1u << (t & 31)) - 1u;
    int i4 = (b * 256 + t) * 4;
    #pragma unroll
    for (int r = 0; r < 4; r++) {
        unsigned m = __match_any_sync(0xffffffffu, vv[r]);
        int leader = __ffs(m) - 1;
        int base = 0;
        if ((t & 31) == leader) base = atomicAdd(&s_cnt[vv[r]], __popc(m));
        base = __shfl_sync(0xffffffffu, base, leader);
        g_perm[g_base[b * NEXP + vv[r]] + base + __popc(m & lt)] = i4 + r;
    }
}

// ---------------- helpers ----------------
__device__ __forceinline__ uint32_t smem_u32(const void* p) {
    uint32_t a;
    asm("{ .reg .u64 t; cvta.to.shared.u64 t, %1; cvt.u32.u64 %0, t; }" : "=r"(a) : "l"(p));
    return a;
}
__device__ __forceinline__ uint32_t bf2(float a, float b) {
    uint32_t r;
    asm("cvt.rn.bf16x2.f32 %0, %1, %2;" : "=r"(r) : "f"(b), "f"(a));
    return r;
}
__device__ __forceinline__ float bfr(float x) {
    __nv_bfloat16 h = __float2bfloat16(x);
    return x - __bfloat162float(h);
}
#define CP16(dst, src) \
    asm volatile("cp.async.ca.shared.global [%0], [%1], 16;" :: "r"(dst), "l"(src))
#define CP_COMMIT() asm volatile("cp.async.commit_group;" ::: "memory")
#define CP_WAIT0()  asm volatile("cp.async.wait_group 0;" ::: "memory")

#define LDSM4(d, addr) \
    asm volatile("ldmatrix.sync.aligned.m8n8.x4.shared.b16 {%0,%1,%2,%3}, [%4];" \
        : "=r"((d)[0]), "=r"((d)[1]), "=r"((d)[2]), "=r"((d)[3]) : "r"(addr))

// NOTE: non-volatile -> ptxas may interleave/software-pipeline the MMA stream
#define MMA(c, a, b0, b1) \
    asm("mma.sync.aligned.m16n8k16.row.col.f32.bf16.bf16.f32 " \
        "{%0,%1,%2,%3},{%4,%5,%6,%7},{%8,%9},{%0,%1,%2,%3};" \
        : "+f"((c)[0]), "+f"((c)[1]), "+f"((c)[2]), "+f"((c)[3]) \
        : "r"((a)[0]), "r"((a)[1]), "r"((a)[2]), "r"((a)[3]), "r"(b0), "r"(b1))

__device__ __forceinline__ void stageW(uint32_t swb, const __nv_bfloat16* gw,
                                       int tid, int nW) {
    const char* src = (const char*)gw;
    int total = nW * 8;
    #pragma unroll 4
    for (int i = tid; i < total; i += NTHR) {
        int n = i >> 3, j = i & 7;
        uint32_t d = n * (HPAD * 2) + j * 16;
        int s = (n * 64 + j * 8) * 2;
        CP16(swb + d, src + s);
        CP16(swb + 9216 + d, src + 8192 + s);
    }
}

// 12 MMAs, interleaved over 4 independent accumulator chains (A0,A1,B0,B1)
#define MMA12I(aA, aB, fhA, flA, fhB, flB, bh, bl) do {  \
    MMA((aA)[0], fhA, (bh)[0], (bh)[1]);                 \
    MMA((aA)[1], fhA, (bh)[2], (bh)[3]);                 \
    MMA((aB)[0], fhB, (bh)[0], (bh)[1]);                 \
    MMA((aB)[1], fhB, (bh)[2], (bh)[3]);                 \
    MMA((aA)[0], fhA, (bl)[0], (bl)[1]);                 \
    MMA((aA)[1], fhA, (bl)[2], (bl)[3]);                 \
    MMA((aB)[0], fhB, (bl)[0], (bl)[1]);                 \
    MMA((aB)[1], fhB, (bl)[2], (bl)[3]);                 \
    MMA((aA)[0], flA, (bh)[0], (bh)[1]);                 \
    MMA((aA)[1], flA, (bh)[2], (bh)[3]);                 \
    MMA((aB)[0], flB, (bh)[0], (bh)[1]);                 \
    MMA((aB)[1], flB, (bh)[2], (bh)[3]);                 \
} while (0)

// ---------------- fused MoE (32 rows/warp, register activations) ----------------
__global__ void __launch_bounds__(NTHR, 3) k_moe(
    const float* __restrict__ X,
    const float* __restrict__ b1, const float* __restrict__ b2,
    const float* __restrict__ b3, const float* __restrict__ b4,
    const float* __restrict__ b5, const float* __restrict__ b6,
    float* __restrict__ out)
{
    extern __shared__ char smem[];
    const int tid = threadIdx.x, wid = tid >> 5, lane = tid & 31;
    const int e = blockIdx.y, tile = blockIdx.x;
    const int off = g_offsets[e];
    const int cnt = g_offsets[e + 1] - off;
    if (tile * ROWS >= cnt) return;
    const int nrows = min(ROWS, cnt - tile * ROWS);

    const uint32_t sb = smem_u32(smem);
    const uint32_t wbuf[2] = { sb, sb + SWSZ };
    float* sB = (float*)(smem + SBIAS);

    const __nv_bfloat16* gwE = g_w + (size_t)e * 9 * 8192;

    stageW(wbuf[0], gwE, tid, 64);
    CP_COMMIT();

    if (tid < 64) {
        sB[tid]       = b1[e * HID + tid];
        sB[64 + tid]  = b2[e * HID + tid];
        sB[128 + tid] = b3[e * HID + tid];
        sB[192 + tid] = b4[e * HID + tid];
        sB[256 + tid] = b5[e * HID + tid];
    }
    if (tid < 32) sB[320 + tid] = (tid < ACT) ? b6[e * ACT + tid] : 0.f;

    const uint32_t bRowL = (uint32_t)((lane & 7) + ((lane >> 4) & 1) * 8);
    const uint32_t bKof  = ((lane >> 3) & 1) * 8;

    const int erow = wid * 32 + (lane >> 2);
    int pr[4];
    const float* xr[4];
    #pragma unroll
    for (int q = 0; q < 4; q++) {
        int rr = erow + q * 8;
        pr[q] = (rr < nrows) ? g_perm[off + tile * ROWS + rr] : -1;
        xr[q] = X + (size_t)((pr[q] >= 0) ? pr[q] : g_perm[off]) * DIM;
    }
    const int cofL = (lane & 3) * 2;
    const int cofH = 8 + cofL;

    float accA[8][4], accB[8][4];
    #pragma unroll
    for (int i = 0; i < 8; i++)
        #pragma unroll
        for (int j = 0; j < 4; j++) { accA[i][j] = 0.f; accB[i][j] = 0.f; }

    float2 cur[8];
    #pragma unroll
    for (int q = 0; q < 2; q++) {
        cur[4 * q + 0] = *(const float2*)(xr[2 * q + 0] + cofL);
        cur[4 * q + 1] = *(const float2*)(xr[2 * q + 1] + cofL);
        cur[4 * q + 2] = *(const float2*)(xr[2 * q + 0] + cofH);
        cur[4 * q + 3] = *(const float2*)(xr[2 * q + 1] + cofH);
    }

    // ============ layer 1: 4 chunks of K=64 ============
    for (int c = 0; c < 4; c++) {
        CP_WAIT0();
        __syncthreads();
        stageW(wbuf[(c + 1) & 1], gwE + (c + 1) * 8192, tid, 64);
        CP_COMMIT();
        const uint32_t wb_ = wbuf[c & 1];
        #pragma unroll
        for (int ks = 0; ks < 4; ks++) {
            uint32_t fhA[4], flA[4], fhB[4], flB[4];
            #pragma unroll
            for (int q = 0; q < 4; q++) {
                float2 dA = cur[q], dB = cur[4 + q];
                fhA[q] = bf2(dA.x, dA.y);
                flA[q] = bf2(bfr(dA.x), bfr(dA.y));
                fhB[q] = bf2(dB.x, dB.y);
                flB[q] = bf2(bfr(dB.x), bfr(dB.y));
            }
            if (!(c == 3 && ks == 3)) {
                int kb = c * 64 + (ks + 1) * 16;
                if (ks == 3) kb = (c + 1) * 64;
                #pragma unroll
                for (int q = 0; q < 2; q++) {
                    cur[4 * q + 0] = *(const float2*)(xr[2 * q + 0] + kb + cofL);
                    cur[4 * q + 1] = *(const float2*)(xr[2 * q + 1] + kb + cofL);
                    cur[4 * q + 2] = *(const float2*)(xr[2 * q + 0] + kb + cofH);
                    cur[4 * q + 3] = *(const float2*)(xr[2 * q + 1] + kb + cofH);
                }
            }
            uint32_t k0 = ks * 16;
            #pragma unroll
            for (int p = 0; p < 4; p++) {
                uint32_t boff = ((p * 16 + bRowL) * HPAD + k0 + bKof) * 2;
                uint32_t bh[4], bl[4];
                LDSM4(bh, wb_ + boff);
                LDSM4(bl, wb_ + 9216 + boff);
                MMA12I((accA + 2 * p), (accB + 2 * p), fhA, flA, fhB, flB, bh, bl);
            }
        }
    }

    // ============ layers 2..5 (stages 4..7) ============
    for (int s = 4; s < 8; s++) {
        CP_WAIT0();
        __syncthreads();
        stageW(wbuf[(s + 1) & 1], gwE + (s + 1) * 8192, tid, (s == 7) ? 32 : 64);
        CP_COMMIT();
        const float* bb = sB + (s - 4) * 64;
        uint32_t fhA[4][4], flA[4][4], fhB[4][4], flB[4][4];
        #pragma unroll
        for (int kt = 0; kt < 4; kt++) {
            #pragma unroll
            for (int h = 0; h < 2; h++) {
                int nt = 2 * kt + h;
                float b0v = bb[nt * 8 + cofL], b1v = bb[nt * 8 + cofL + 1];
                float v0 = fmaxf(accA[nt][0] + b0v, 0.f);
                float v1 = fmaxf(accA[nt][1] + b1v, 0.f);
                float v2 = fmaxf(accA[nt][2] + b0v, 0.f);
                float v3 = fmaxf(accA[nt][3] + b1v, 0.f);
                fhA[kt][2 * h]     = bf2(v0, v1);
                fhA[kt][2 * h + 1] = bf2(v2, v3);
                flA[kt][2 * h]     = bf2(bfr(v0), bfr(v1));
                flA[kt][2 * h + 1] = bf2(bfr(v2), bfr(v3));
                float w0 = fmaxf(accB[nt][0] + b0v, 0.f);
                float w1 = fmaxf(accB[nt][1] + b1v, 0.f);
                float w2 = fmaxf(accB[nt][2] + b0v, 0.f);
                float w3 = fmaxf(accB[nt][3] + b1v, 0.f);
                fhB[kt][2 * h]     = bf2(w0, w1);
                fhB[kt][2 * h + 1] = bf2(w2, w3);
                flB[kt][2 * h]     = bf2(bfr(w0), bfr(w1));
                flB[kt][2 * h + 1] = bf2(bfr(w2), bfr(w3));
            }
        }
        #pragma unroll
        for (int i = 0; i < 8; i++)
            #pragma unroll
            for (int j = 0; j < 4; j++) { accA[i][j] = 0.f; accB[i][j] = 0.f; }
        #pragma unroll
        for (int ks = 0; ks < 4; ks++) {
            uint32_t k0 = ks * 16;
            #pragma unroll
            for (int p = 0; p < 4; p++) {
                uint32_t boff = ((p * 16 + bRowL) * HPAD + k0 + bKof) * 2;
                uint32_t bh[4], bl[4];
                LDSM4(bh, wbuf[s & 1] + boff);
                LDSM4(bl, wbuf[s & 1] + 9216 + boff);
                MMA12I((accA + 2 * p), (accB + 2 * p),
                       fhA[ks], flA[ks], fhB[ks], flB[ks], bh, bl);
            }
        }
    }

    // ============ layer 6 (stage 8) ============
    CP_WAIT0();
    __syncthreads();
    {
        const float* bb = sB + 256;
        uint32_t fhA[4][4], flA[4][4], fhB[4][4], flB[4][4];
        #pragma unroll
        for (int kt = 0; kt < 4; kt++) {
            #pragma unroll
            for (int h = 0; h < 2; h++) {
                int nt = 2 * kt + h;
                float b0v = bb[nt * 8 + cofL], b1v = bb[nt * 8 + cofL + 1];
                float v0 = fmaxf(accA[nt][0] + b0v, 0.f);
                float v1 = fmaxf(accA[nt][1] + b1v, 0.f);
                float v2 = fmaxf(accA[nt][2] + b0v, 0.f);
                float v3 = fmaxf(accA[nt][3] + b1v, 0.f);
                fhA[kt][2 * h]     = bf2(v0, v1);
                fhA[kt][2 * h + 1] = bf2(v2, v3);
                flA[kt][2 * h]     = bf2(bfr(v0), bfr(v1));
                flA[kt][2 * h + 1] = bf2(bfr(v2), bfr(v3));
                float w0 = fmaxf(accB[nt][0] + b0v, 0.f);
                float w1 = fmaxf(accB[nt][1] + b1v, 0.f);
                float w2 = fmaxf(accB[nt][2] + b0v, 0.f);
                float w3 = fmaxf(accB[nt][3] + b1v, 0.f);
                fhB[kt][2 * h]     = bf2(w0, w1);
                fhB[kt][2 * h + 1] = bf2(w2, w3);
                flB[kt][2 * h]     = bf2(bfr(w0), bfr(w1));
                flB[kt][2 * h + 1] = bf2(bfr(w2), bfr(w3));
            }
        }
        float acc6A[4][4], acc6B[4][4];
        #pragma unroll
        for (int i = 0; i < 4; i++)
            #pragma unroll
            for (int j = 0; j < 4; j++) { acc6A[i][j] = 0.f; acc6B[i][j] = 0.f; }

        const uint32_t wb_ = wbuf[0];
        #pragma unroll
        for (int ks = 0; ks < 4; ks++) {
            uint32_t k0 = ks * 16;
            #pragma unroll
            for (int p = 0; p < 2; p++) {
                uint32_t boff = ((p * 16 + bRowL) * HPAD + k0 + bKof) * 2;
                uint32_t bh[4], bl[4];
                LDSM4(bh, wb_ + boff);
                LDSM4(bl, wb_ + 9216 + boff);
                MMA12I((acc6A + 2 * p), (acc6B + 2 * p),
                       fhA[ks], flA[ks], fhB[ks], flB[ks], bh, bl);
            }
        }

        const float* b6b = sB + 320;
        #pragma unroll
        for (int nt = 0; nt < 3; nt++) {
            int c0 = nt * 8 + cofL;
            if (c0 + 1 < ACT) {
                float b0v = b6b[c0], b1v = b6b[c0 + 1];
                if (pr[0] >= 0) {
                    out[(size_t)pr[0] * ACT + c0]     = acc6A[nt][0] + b0v;
                    out[(size_t)pr[0] * ACT + c0 + 1] = acc6A[nt][1] + b1v;
                }
                if (pr[1] >= 0) {
                    out[(size_t)pr[1] * ACT + c0]     = acc6A[nt][2] + b0v;
                    out[(size_t)pr[1] * ACT + c0 + 1] = acc6A[nt][3] + b1v;
                }
                if (pr[2] >= 0) {
                    out[(size_t)pr[2] * ACT + c0]     = acc6B[nt][0] + b0v;
                    out[(size_t)pr[2] * ACT + c0 + 1] = acc6B[nt][1] + b1v;
                }
                if (pr[3] >= 0) {
                    out[(size_t)pr[3] * ACT + c0]     = acc6B[nt][2] + b0v;
                    out[(size_t)pr[3] * ACT + c0 + 1] = acc6B[nt][3] + b1v;
                }
            }
        }
    }
}

extern "C" void kernel_launch(void* const* d_in, const int* in_sizes, int n_in,
                              void* d_out, int out_size) {
    const float* X  = (const float*)d_in[0];
    const int*   rm = (const int*)d_in[1];
    const float* W1 = (const float*)d_in[2];  const float* b1 = (const float*)d_in[3];
    const float* W2 = (const float*)d_in[4];  const float* b2 = (const float*)d_in[5];
    const float* W3 = (const float*)d_in[6];  const float* b3 = (const float*)d_in[7];
    const float* W4 = (const float*)d_in[8];  const float* b4 = (const float*)d_in[9];
    const float* W5 = (const float*)d_in[10]; const float* b5 = (const float*)d_in[11];
    const float* W6 = (const float*)d_in[12]; const float* b6 = (const float*)d_in[13];
    float* out = (float*)d_out;

    cudaFuncSetAttribute(k_moe, cudaFuncAttributeMaxDynamicSharedMemorySize, SMEM_TOTAL);

    k_pre1<<<HB + WB, 256>>>((const int4*)rm, W1, W2, W3, W4, W5, W6);
    k_pre2<<<1, 32>>>();
    k_scatter<<<HB, 256>>>((const int4*)rm);

    dim3 grid(NB / ROWS, NEXP);
    k_moe<<<grid, NTHR, SMEM_TOTAL>>>(X, b1, b2, b3, b4, b5, b6, out);
}

// round 10
// speedup vs baseline: 1.5078x; 1.0468x over previous
#include <cuda_runtime.h>
#include <cuda_fp16.h>
#include <cstdint>

#define NB    65536
#define DIM   256
#define HID   64
#define ACT   18
#define NEXP  8
#define ROWS  128
#define NTHR  128
#define HPAD  72        // halves per row stride (144B) -> conflict-free ldmatrix

// smem: W double buffer + bias
#define SWSZ   18432
#define SBIAS  (2 * SWSZ)
#define SMEM_TOTAL (SBIAS + 1408)

// ---------------- scratch ----------------
#define HB 64
__device__ int g_part[HB * NEXP];
__device__ int g_base[HB * NEXP];
__device__ int g_offsets[NEXP + 1];
__device__ int g_perm[NB];
// per expert 9 slots (W1 c0..c3, W2..W5, W6) of 8192 halves:
// hi plane [0,4096), lo plane [4096,8192); layout [n][64 k]
__device__ __align__(16) __half g_w[NEXP * 9 * 8192];

#define WCONV_TOTAL (NEXP * 34816)
#define WB ((WCONV_TOTAL + 1023) / 1024)

// ---------------- fused hist + wconv ----------------
__global__ void k_pre1(const int4* __restrict__ rm,
                       const float* __restrict__ W1, const float* __restrict__ W2,
                       const float* __restrict__ W3, const float* __restrict__ W4,
                       const float* __restrict__ W5, const float* __restrict__ W6) {
    int b = blockIdx.x, t = threadIdx.x;
    if (b < HB) {
        __shared__ int s_cnt[NEXP];
        if (t < NEXP) s_cnt[t] = 0;
        __syncthreads();
        int4 v = rm[b * 256 + t];
        int vv[4] = { v.x, v.y, v.z, v.w };
        #pragma unroll
        for (int r = 0; r < 4; r++) {
            unsigned m = __match_any_sync(0xffffffffu, vv[r]);
            if ((t & 31) == __ffs(m) - 1) atomicAdd(&s_cnt[vv[r]], __popc(m));
        }
        __syncthreads();
        if (t < NEXP) g_part[b * NEXP + t] = s_cnt[t];
    } else {
        int wb = b - HB;
        #pragma unroll
        for (int j = 0; j < 4; j++) {
            int idx = wb * 1024 + j * 256 + t;
            if (idx >= WCONV_TOTAL) break;
            int e = idx / 34816, r = idx % 34816;
            float w;
            int dst;
            if (r < 16384) {
                int c = r >> 12, nk = r & 4095, n = nk >> 6, k = nk & 63;
                w = W1[((size_t)e * 256 + c * 64 + k) * 64 + n];
                dst = (e * 9 + c) * 8192 + nk;
            } else if (r < 32768) {
                int l = (r - 16384) >> 12, nk = (r - 16384) & 4095, n = nk >> 6, k = nk & 63;
                const float* Wl = (l == 0) ? W2 : (l == 1) ? W3 : (l == 2) ? W4 : W5;
                w = Wl[((size_t)e * 64 + k) * 64 + n];
                dst = (e * 9 + 4 + l) * 8192 + nk;
            } else {
                int nk = r - 32768, n = nk >> 6, k = nk & 63;
                w = (n < ACT) ? W6[((size_t)e * 64 + k) * ACT + n] : 0.f;
                dst = (e * 9 + 8) * 8192 + nk;
            }
            __half h = __float2half_rn(w);
            g_w[dst] = h;
            g_w[dst + 4096] = __float2half_rn(w - __half2float(h));
        }
    }
}

__global__ void k_pre2() {
    __shared__ int cnts[NEXP];
    int t = threadIdx.x;
    if (t < NEXP) {
        int run = 0;
        for (int b = 0; b < HB; b++) run += g_part[b * NEXP + t];
        cnts[t] = run;
    }
    __syncthreads();
    if (t == 0) {
        int off = 0;
        for (int e = 0; e < NEXP; e++) { g_offsets[e] = off; off += cnts[e]; }
        g_offsets[NEXP] = off;
    }
    __syncthreads();
    if (t < NEXP) {
        int run = g_offsets[t];
        for (int b = 0; b < HB; b++) {
            g_base[b * NEXP + t] = run;
            run += g_part[b * NEXP + t];
        }
    }
}

__global__ void k_scatter(const int4* __restrict__ rm) {
    __shared__ int s_cnt[NEXP];
    int b = blockIdx.x, t = threadIdx.x;
    if (t < NEXP) s_cnt[t] = 0;
    __syncthreads();
    int4 v = rm[b * 256 + t];
    int vv[4] = { v.x, v.y, v.z, v.w };
    unsigned lt = (1u << (t & 31)) - 1u;
    int i4 = (b * 256 + t) * 4;
    #pragma unroll
    for (int r = 0; r < 4; r++) {
        unsigned m = __match_any_sync(0xffffffffu, vv[r]);
        int leader = __ffs(m) - 1;
        int base = 0;
        if ((t & 31) == leader) base = atomicAdd(&s_cnt[vv[r]], __popc(m));
        base = __shfl_sync(0xffffffffu, base, leader);
        g_perm[g_base[b * NEXP + vv[r]] + base + __popc(m & lt)] = i4 + r;
    }
}

// ---------------- helpers ----------------
__device__ __forceinline__ uint32_t smem_u32(const void* p) {
    uint32_t a;
    asm("{ .reg .u64 t; cvta.to.shared.u64 t, %1; cvt.u32.u64 %0, t; }" : "=r"(a) : "l"(p));
    return a;
}
// pack: {lo16 = f16(a), hi16 = f16(b)}
__device__ __forceinline__ uint32_t pk2(float a, float b) {
    uint32_t r;
    asm("cvt.rn.f16x2.f32 %0, %1, %2;" : "=r"(r) : "f"(b), "f"(a));
    return r;
}
#define CP16(dst, src) \
    asm volatile("cp.async.ca.shared.global [%0], [%1], 16;" :: "r"(dst), "l"(src))
#define CP_COMMIT() asm volatile("cp.async.commit_group;" ::: "memory")
#define CP_WAIT0()  asm volatile("cp.async.wait_group 0;" ::: "memory")

#define LDSM4(d, addr) \
    asm volatile("ldmatrix.sync.aligned.m8n8.x4.shared.b16 {%0,%1,%2,%3}, [%4];" \
        : "=r"((d)[0]), "=r"((d)[1]), "=r"((d)[2]), "=r"((d)[3]) : "r"(addr))

// non-volatile: ptxas may interleave/software-pipeline the MMA stream
#define MMA(c, a, b0, b1) \
    asm("mma.sync.aligned.m16n8k16.row.col.f32.f16.f16.f32 " \
        "{%0,%1,%2,%3},{%4,%5,%6,%7},{%8,%9},{%0,%1,%2,%3};" \
        : "+f"((c)[0]), "+f"((c)[1]), "+f"((c)[2]), "+f"((c)[3]) \
        : "r"((a)[0]), "r"((a)[1]), "r"((a)[2]), "r"((a)[3]), "r"(b0), "r"(b1))

__device__ __forceinline__ void stageW(uint32_t swb, const __half* gw,
                                       int tid, int nW) {
    const char* src = (const char*)gw;
    int total = nW * 8;
    #pragma unroll 4
    for (int i = tid; i < total; i += NTHR) {
        int n = i >> 3, j = i & 7;
        uint32_t d = n * (HPAD * 2) + j * 16;
        int s = (n * 64 + j * 8) * 2;
        CP16(swb + d, src + s);
        CP16(swb + 9216 + d, src + 8192 + s);
    }
}

// 8 MMAs interleaved over 4 independent accumulator chains
#define MMA8I(aA, aB, fA, fB, bh, bl) do {               \
    MMA((aA)[0], fA, (bh)[0], (bh)[1]);                  \
    MMA((aA)[1], fA, (bh)[2], (bh)[3]);                  \
    MMA((aB)[0], fB, (bh)[0], (bh)[1]);                  \
    MMA((aB)[1], fB, (bh)[2], (bh)[3]);                  \
    MMA((aA)[0], fA, (bl)[0], (bl)[1]);                  \
    MMA((aA)[1], fA, (bl)[2], (bl)[3]);                  \
    MMA((aB)[0], fB, (bl)[0], (bl)[1]);                  \
    MMA((aB)[1], fB, (bl)[2], (bl)[3]);                  \
} while (0)

// ---------------- fused MoE (32 rows/warp, fp16 2-term) ----------------
__global__ void __launch_bounds__(NTHR, 3) k_moe(
    const float* __restrict__ X,
    const float* __restrict__ b1, const float* __restrict__ b2,
    const float* __restrict__ b3, const float* __restrict__ b4,
    const float* __restrict__ b5, const float* __restrict__ b6,
    float* __restrict__ out)
{
    extern __shared__ char smem[];
    const int tid = threadIdx.x, wid = tid >> 5, lane = tid & 31;
    const int e = blockIdx.y, tile = blockIdx.x;
    const int off = g_offsets[e];
    const int cnt = g_offsets[e + 1] - off;
    if (tile * ROWS >= cnt) return;
    const int nrows = min(ROWS, cnt - tile * ROWS);

    const uint32_t sb = smem_u32(smem);
    const uint32_t wbuf[2] = { sb, sb + SWSZ };
    float* sB = (float*)(smem + SBIAS);

    const __half* gwE = g_w + (size_t)e * 9 * 8192;

    stageW(wbuf[0], gwE, tid, 64);
    CP_COMMIT();

    if (tid < 64) {
        sB[tid]       = b1[e * HID + tid];
        sB[64 + tid]  = b2[e * HID + tid];
        sB[128 + tid] = b3[e * HID + tid];
        sB[192 + tid] = b4[e * HID + tid];
        sB[256 + tid] = b5[e * HID + tid];
    }
    if (tid < 32) sB[320 + tid] = (tid < ACT) ? b6[e * ACT + tid] : 0.f;

    const uint32_t bRowL = (uint32_t)((lane & 7) + ((lane >> 4) & 1) * 8);
    const uint32_t bKof  = ((lane >> 3) & 1) * 8;

    const int erow = wid * 32 + (lane >> 2);
    int pr[4];
    const float* xr[4];
    #pragma unroll
    for (int q = 0; q < 4; q++) {
        int rr = erow + q * 8;
        pr[q] = (rr < nrows) ? g_perm[off + tile * ROWS + rr] : -1;
        xr[q] = X + (size_t)((pr[q] >= 0) ? pr[q] : g_perm[off]) * DIM;
    }
    const int cofL = (lane & 3) * 2;
    const int cofH = 8 + cofL;

    float accA[8][4], accB[8][4];
    #pragma unroll
    for (int i = 0; i < 8; i++)
        #pragma unroll
        for (int j = 0; j < 4; j++) { accA[i][j] = 0.f; accB[i][j] = 0.f; }

    float2 cur[8];
    #pragma unroll
    for (int q = 0; q < 2; q++) {
        cur[4 * q + 0] = *(const float2*)(xr[2 * q + 0] + cofL);
        cur[4 * q + 1] = *(const float2*)(xr[2 * q + 1] + cofL);
        cur[4 * q + 2] = *(const float2*)(xr[2 * q + 0] + cofH);
        cur[4 * q + 3] = *(const float2*)(xr[2 * q + 1] + cofH);
    }

    // ============ layer 1: 4 chunks of K=64 ============
    for (int c = 0; c < 4; c++) {
        CP_WAIT0();
        __syncthreads();
        stageW(wbuf[(c + 1) & 1], gwE + (c + 1) * 8192, tid, 64);
        CP_COMMIT();
        const uint32_t wb_ = wbuf[c & 1];
        #pragma unroll
        for (int ks = 0; ks < 4; ks++) {
            uint32_t fA[4], fB[4];
            #pragma unroll
            for (int q = 0; q < 4; q++) {
                fA[q] = pk2(cur[q].x, cur[q].y);
                fB[q] = pk2(cur[4 + q].x, cur[4 + q].y);
            }
            if (!(c == 3 && ks == 3)) {
                int kb = c * 64 + (ks + 1) * 16;
                if (ks == 3) kb = (c + 1) * 64;
                #pragma unroll
                for (int q = 0; q < 2; q++) {
                    cur[4 * q + 0] = *(const float2*)(xr[2 * q + 0] + kb + cofL);
                    cur[4 * q + 1] = *(const float2*)(xr[2 * q + 1] + kb + cofL);
                    cur[4 * q + 2] = *(const float2*)(xr[2 * q + 0] + kb + cofH);
                    cur[4 * q + 3] = *(const float2*)(xr[2 * q + 1] + kb + cofH);
                }
            }
            uint32_t k0 = ks * 16;
            #pragma unroll
            for (int p = 0; p < 4; p++) {
                uint32_t boff = ((p * 16 + bRowL) * HPAD + k0 + bKof) * 2;
                uint32_t bh[4], bl[4];
                LDSM4(bh, wb_ + boff);
                LDSM4(bl, wb_ + 9216 + boff);
                MMA8I((accA + 2 * p), (accB + 2 * p), fA, fB, bh, bl);
            }
        }
    }

    // ============ layers 2..5 (stages 4..7) ============
    for (int s = 4; s < 8; s++) {
        CP_WAIT0();
        __syncthreads();
        stageW(wbuf[(s + 1) & 1], gwE + (s + 1) * 8192, tid, (s == 7) ? 32 : 64);
        CP_COMMIT();
        const float* bb = sB + (s - 4) * 64;
        uint32_t fA[4][4], fB[4][4];
        #pragma unroll
        for (int kt = 0; kt < 4; kt++) {
            #pragma unroll
            for (int h = 0; h < 2; h++) {
                int nt = 2 * kt + h;
                float b0v = bb[nt * 8 + cofL], b1v = bb[nt * 8 + cofL + 1];
                float v0 = fmaxf(accA[nt][0] + b0v, 0.f);
                float v1 = fmaxf(accA[nt][1] + b1v, 0.f);
                float v2 = fmaxf(accA[nt][2] + b0v, 0.f);
                float v3 = fmaxf(accA[nt][3] + b1v, 0.f);
                fA[kt][2 * h]     = pk2(v0, v1);
                fA[kt][2 * h + 1] = pk2(v2, v3);
                float w0 = fmaxf(accB[nt][0] + b0v, 0.f);
                float w1 = fmaxf(accB[nt][1] + b1v, 0.f);
                float w2 = fmaxf(accB[nt][2] + b0v, 0.f);
                float w3 = fmaxf(accB[nt][3] + b1v, 0.f);
                fB[kt][2 * h]     = pk2(w0, w1);
                fB[kt][2 * h + 1] = pk2(w2, w3);
            }
        }
        #pragma unroll
        for (int i = 0; i < 8; i++)
            #pragma unroll
            for (int j = 0; j < 4; j++) { accA[i][j] = 0.f; accB[i][j] = 0.f; }
        #pragma unroll
        for (int ks = 0; ks < 4; ks++) {
            uint32_t k0 = ks * 16;
            #pragma unroll
            for (int p = 0; p < 4; p++) {
                uint32_t boff = ((p * 16 + bRowL) * HPAD + k0 + bKof) * 2;
                uint32_t bh[4], bl[4];
                LDSM4(bh, wbuf[s & 1] + boff);
                LDSM4(bl, wbuf[s & 1] + 9216 + boff);
                MMA8I((accA + 2 * p), (accB + 2 * p), fA[ks], fB[ks], bh, bl);
            }
        }
    }

    // ============ layer 6 (stage 8) ============
    CP_WAIT0();
    __syncthreads();
    {
        const float* bb = sB + 256;
        uint32_t fA[4][4], fB[4][4];
        #pragma unroll
        for (int kt = 0; kt < 4; kt++) {
            #pragma unroll
            for (int h = 0; h < 2; h++) {
                int nt = 2 * kt + h;
                float b0v = bb[nt * 8 + cofL], b1v = bb[nt * 8 + cofL + 1];
                float v0 = fmaxf(accA[nt][0] + b0v, 0.f);
                float v1 = fmaxf(accA[nt][1] + b1v, 0.f);
                float v2 = fmaxf(accA[nt][2] + b0v, 0.f);
                float v3 = fmaxf(accA[nt][3] + b1v, 0.f);
                fA[kt][2 * h]     = pk2(v0, v1);
                fA[kt][2 * h + 1] = pk2(v2, v3);
                float w0 = fmaxf(accB[nt][0] + b0v, 0.f);
                float w1 = fmaxf(accB[nt][1] + b1v, 0.f);
                float w2 = fmaxf(accB[nt][2] + b0v, 0.f);
                float w3 = fmaxf(accB[nt][3] + b1v, 0.f);
                fB[kt][2 * h]     = pk2(w0, w1);
                fB[kt][2 * h + 1] = pk2(w2, w3);
            }
        }
        float acc6A[4][4], acc6B[4][4];
        #pragma unroll
        for (int i = 0; i < 4; i++)
            #pragma unroll
            for (int j = 0; j < 4; j++) { acc6A[i][j] = 0.f; acc6B[i][j] = 0.f; }

        const uint32_t wb_ = wbuf[0];
        #pragma unroll
        for (int ks = 0; ks < 4; ks++) {
            uint32_t k0 = ks * 16;
            #pragma unroll
            for (int p = 0; p < 2; p++) {
                uint32_t boff = ((p * 16 + bRowL) * HPAD + k0 + bKof) * 2;
                uint32_t bh[4], bl[4];
                LDSM4(bh, wb_ + boff);
                LDSM4(bl, wb_ + 9216 + boff);
                MMA8I((acc6A + 2 * p), (acc6B + 2 * p), fA[ks], fB[ks], bh, bl);
            }
        }

        const float* b6b = sB + 320;
        #pragma unroll
        for (int nt = 0; nt < 3; nt++) {
            int c0 = nt * 8 + cofL;
            if (c0 + 1 < ACT) {
                float b0v = b6b[c0], b1v = b6b[c0 + 1];
                if (pr[0] >= 0) {
                    out[(size_t)pr[0] * ACT + c0]     = acc6A[nt][0] + b0v;
                    out[(size_t)pr[0] * ACT + c0 + 1] = acc6A[nt][1] + b1v;
                }
                if (pr[1] >= 0) {
                    out[(size_t)pr[1] * ACT + c0]     = acc6A[nt][2] + b0v;
                    out[(size_t)pr[1] * ACT + c0 + 1] = acc6A[nt][3] + b1v;
                }
                if (pr[2] >= 0) {
                    out[(size_t)pr[2] * ACT + c0]     = acc6B[nt][0] + b0v;
                    out[(size_t)pr[2] * ACT + c0 + 1] = acc6B[nt][1] + b1v;
                }
                if (pr[3] >= 0) {
                    out[(size_t)pr[3] * ACT + c0]     = acc6B[nt][2] + b0v;
                    out[(size_t)pr[3] * ACT + c0 + 1] = acc6B[nt][3] + b1v;
                }
            }
        }
    }
}

extern "C" void kernel_launch(void* const* d_in, const int* in_sizes, int n_in,
                              void* d_out, int out_size) {
    const float* X  = (const float*)d_in[0];
    const int*   rm = (const int*)d_in[1];
    const float* W1 = (const float*)d_in[2];  const float* b1 = (const float*)d_in[3];
    const float* W2 = (const float*)d_in[4];  const float* b2 = (const float*)d_in[5];
    const float* W3 = (const float*)d_in[6];  const float* b3 = (const float*)d_in[7];
    const float* W4 = (const float*)d_in[8];  const float* b4 = (const float*)d_in[9];
    const float* W5 = (const float*)d_in[10]; const float* b5 = (const float*)d_in[11];
    const float* W6 = (const float*)d_in[12]; const float* b6 = (const float*)d_in[13];
    float* out = (float*)d_out;

    cudaFuncSetAttribute(k_moe, cudaFuncAttributeMaxDynamicSharedMemorySize, SMEM_TOTAL);

    k_pre1<<<HB + WB, 256>>>((const int4*)rm, W1, W2, W3, W4, W5, W6);
    k_pre2<<<1, 32>>>();
    k_scatter<<<HB, 256>>>((const int4*)rm);

    dim3 grid(NB / ROWS, NEXP);
    k_moe<<<grid, NTHR, SMEM_TOTAL>>>(X, b1, b2, b3, b4, b5, b6, out);
}

// round 11
// speedup vs baseline: 1.8498x; 1.2268x over previous
#include <cuda_runtime.h>
#include <cuda_fp16.h>
#include <cstdint>

#define NB    65536
#define DIM   256
#define HID   64
#define ACT   18
#define NEXP  8
#define ROWS  128
#define NTHR  128
#define HPAD  72        // halves per row stride (144B) -> conflict-free ldmatrix

// smem: W double buffer + bias
#define SWSZ   18432
#define SBIAS  (2 * SWSZ)
#define SMEM_TOTAL (SBIAS + 1408)

// ---------------- scratch ----------------
#define HB 64
__device__ int g_part[HB * NEXP];
__device__ int g_offsets[NEXP + 1];
__device__ int g_perm[NB];
// per expert 9 slots (W1 c0..c3, W2..W5, W6) of 8192 halves:
// hi plane [0,4096), lo plane [4096,8192); layout [n][64 k]
__device__ __align__(16) __half g_w[NEXP * 9 * 8192];

#define WCONV_TOTAL (NEXP * 34816)
#define WB ((WCONV_TOTAL + 1023) / 1024)

// ---------------- fused hist + wconv ----------------
__global__ void k_pre1(const int4* __restrict__ rm,
                       const float* __restrict__ W1, const float* __restrict__ W2,
                       const float* __restrict__ W3, const float* __restrict__ W4,
                       const float* __restrict__ W5, const float* __restrict__ W6) {
    int b = blockIdx.x, t = threadIdx.x;
    if (b < HB) {
        __shared__ int s_cnt[NEXP];
        if (t < NEXP) s_cnt[t] = 0;
        __syncthreads();
        int4 v = rm[b * 256 + t];
        int vv[4] = { v.x, v.y, v.z, v.w };
        #pragma unroll
        for (int r = 0; r < 4; r++) {
            unsigned m = __match_any_sync(0xffffffffu, vv[r]);
            if ((t & 31) == __ffs(m) - 1) atomicAdd(&s_cnt[vv[r]], __popc(m));
        }
        __syncthreads();
        if (t < NEXP) g_part[b * NEXP + t] = s_cnt[t];
    } else {
        int wb = b - HB;
        #pragma unroll
        for (int j = 0; j < 4; j++) {
            int idx = wb * 1024 + j * 256 + t;
            if (idx >= WCONV_TOTAL) break;
            int e = idx / 34816, r = idx % 34816;
            float w;
            int dst;
            if (r < 16384) {
                int c = r >> 12, nk = r & 4095, n = nk >> 6, k = nk & 63;
                w = W1[((size_t)e * 256 + c * 64 + k) * 64 + n];
                dst = (e * 9 + c) * 8192 + nk;
            } else if (r < 32768) {
                int l = (r - 16384) >> 12, nk = (r - 16384) & 4095, n = nk >> 6, k = nk & 63;
                const float* Wl = (l == 0) ? W2 : (l == 1) ? W3 : (l == 2) ? W4 : W5;
                w = Wl[((size_t)e * 64 + k) * 64 + n];
                dst = (e * 9 + 4 + l) * 8192 + nk;
            } else {
                int nk = r - 32768, n = nk >> 6, k = nk & 63;
                w = (n < ACT) ? W6[((size_t)e * 64 + k) * ACT + n] : 0.f;
                dst = (e * 9 + 8) * 8192 + nk;
            }
            __half h = __float2half_rn(w);
            g_w[dst] = h;
            g_w[dst + 4096] = __float2half_rn(w - __half2float(h));
        }
    }
}

// ---------------- scatter (computes its own prefix from g_part) ----------------
__global__ void k_scatter(const int4* __restrict__ rm) {
    __shared__ int s_base[NEXP];
    __shared__ int s_cnt[NEXP];
    int b = blockIdx.x, t = threadIdx.x;
    if (t < NEXP) {
        int col = 0, pre = 0;
        #pragma unroll
        for (int bb = 0; bb < HB; bb++) {
            int v = g_part[bb * NEXP + t];
            col += v;
            if (bb < b) pre += v;
        }
        // exclusive prefix of col over experts (threads 0..7, warp 0)
        int offs = 0;
        #pragma unroll
        for (int u = 0; u < NEXP; u++) {
            int cv = __shfl_sync(0x000000ffu, col, u);
            if (u < t) offs += cv;
        }
        s_base[t] = offs + pre;
        s_cnt[t] = 0;
        if (b == 0) {
            g_offsets[t] = offs;
            if (t == NEXP - 1) g_offsets[NEXP] = offs + col;
        }
    }
    __syncthreads();
    int4 v = rm[b * 256 + t];
    int vv[4] = { v.x, v.y, v.z, v.w };
    unsigned lt = (1u << (t & 31)) - 1u;
    int i4 = (b * 256 + t) * 4;
    #pragma unroll
    for (int r = 0; r < 4; r++) {
        unsigned m = __match_any_sync(0xffffffffu, vv[r]);
        int leader = __ffs(m) - 1;
        int base = 0;
        if ((t & 31) == leader) base = atomicAdd(&s_cnt[vv[r]], __popc(m));
        base = __shfl_sync(0xffffffffu, base, leader);
        g_perm[s_base[vv[r]] + base + __popc(m & lt)] = i4 + r;
    }
}

// ---------------- helpers ----------------
__device__ __forceinline__ uint32_t smem_u32(const void* p) {
    uint32_t a;
    asm("{ .reg .u64 t; cvta.to.shared.u64 t, %1; cvt.u32.u64 %0, t; }" : "=r"(a) : "l"(p));
    return a;
}
// pack: {lo16 = f16(a), hi16 = f16(b)}
__device__ __forceinline__ uint32_t pk2(float a, float b) {
    uint32_t r;
    asm("cvt.rn.f16x2.f32 %0, %1, %2;" : "=r"(r) : "f"(b), "f"(a));
    return r;
}
#define CP16(dst, src) \
    asm volatile("cp.async.ca.shared.global [%0], [%1], 16;" :: "r"(dst), "l"(src))
#define CP_COMMIT() asm volatile("cp.async.commit_group;" ::: "memory")
#define CP_WAIT0()  asm volatile("cp.async.wait_group 0;" ::: "memory")

#define LDSM4(d, addr) \
    asm volatile("ldmatrix.sync.aligned.m8n8.x4.shared.b16 {%0,%1,%2,%3}, [%4];" \
        : "=r"((d)[0]), "=r"((d)[1]), "=r"((d)[2]), "=r"((d)[3]) : "r"(addr))

// non-volatile: ptxas may interleave/software-pipeline the MMA stream
#define MMA(c, a, b0, b1) \
    asm("mma.sync.aligned.m16n8k16.row.col.f32.f16.f16.f32 " \
        "{%0,%1,%2,%3},{%4,%5,%6,%7},{%8,%9},{%0,%1,%2,%3};" \
        : "+f"((c)[0]), "+f"((c)[1]), "+f"((c)[2]), "+f"((c)[3]) \
        : "r"((a)[0]), "r"((a)[1]), "r"((a)[2]), "r"((a)[3]), "r"(b0), "r"(b1))

__device__ __forceinline__ void stageW(uint32_t swb, const __half* gw,
                                       int tid, int nW) {
    const char* src = (const char*)gw;
    int total = nW * 8;
    #pragma unroll 4
    for (int i = tid; i < total; i += NTHR) {
        int n = i >> 3, j = i & 7;
        uint32_t d = n * (HPAD * 2) + j * 16;
        int s = (n * 64 + j * 8) * 2;
        CP16(swb + d, src + s);
        CP16(swb + 9216 + d, src + 8192 + s);
    }
}

// 8 MMAs interleaved over 4 independent accumulator chains
#define MMA8I(aA, aB, fA, fB, bh, bl) do {               \
    MMA((aA)[0], fA, (bh)[0], (bh)[1]);                  \
    MMA((aA)[1], fA, (bh)[2], (bh)[3]);                  \
    MMA((aB)[0], fB, (bh)[0], (bh)[1]);                  \
    MMA((aB)[1], fB, (bh)[2], (bh)[3]);                  \
    MMA((aA)[0], fA, (bl)[0], (bl)[1]);                  \
    MMA((aA)[1], fA, (bl)[2], (bl)[3]);                  \
    MMA((aB)[0], fB, (bl)[0], (bl)[1]);                  \
    MMA((aB)[1], fB, (bl)[2], (bl)[3]);                  \
} while (0)

// ---------------- fused MoE (32 rows/warp, fp16 2-term) ----------------
__global__ void __launch_bounds__(NTHR, 4) k_moe(
    const float* __restrict__ X,
    const float* __restrict__ b1, const float* __restrict__ b2,
    const float* __restrict__ b3, const float* __restrict__ b4,
    const float* __restrict__ b5, const float* __restrict__ b6,
    float* __restrict__ out)
{
    extern __shared__ char smem[];
    const int tid = threadIdx.x, wid = tid >> 5, lane = tid & 31;
    const int e = blockIdx.y, tile = blockIdx.x;
    const int off = g_offsets[e];
    const int cnt = g_offsets[e + 1] - off;
    if (tile * ROWS >= cnt) return;
    const int nrows = min(ROWS, cnt - tile * ROWS);

    const uint32_t sb = smem_u32(smem);
    const uint32_t wbuf[2] = { sb, sb + SWSZ };
    float* sB = (float*)(smem + SBIAS);

    const __half* gwE = g_w + (size_t)e * 9 * 8192;

    stageW(wbuf[0], gwE, tid, 64);
    CP_COMMIT();

    if (tid < 64) {
        sB[tid]       = b1[e * HID + tid];
        sB[64 + tid]  = b2[e * HID + tid];
        sB[128 + tid] = b3[e * HID + tid];
        sB[192 + tid] = b4[e * HID + tid];
        sB[256 + tid] = b5[e * HID + tid];
    }
    if (tid < 32) sB[320 + tid] = (tid < ACT) ? b6[e * ACT + tid] : 0.f;

    const uint32_t bRowL = (uint32_t)((lane & 7) + ((lane >> 4) & 1) * 8);
    const uint32_t bKof  = ((lane >> 3) & 1) * 8;

    const int erow = wid * 32 + (lane >> 2);
    int pr[4];
    const float* xr[4];
    #pragma unroll
    for (int q = 0; q < 4; q++) {
        int rr = erow + q * 8;
        pr[q] = (rr < nrows) ? g_perm[off + tile * ROWS + rr] : -1;
        xr[q] = X + (size_t)((pr[q] >= 0) ? pr[q] : g_perm[off]) * DIM;
    }
    const int cofL = (lane & 3) * 2;
    const int cofH = 8 + cofL;

    float accA[8][4], accB[8][4];
    #pragma unroll
    for (int i = 0; i < 8; i++)
        #pragma unroll
        for (int j = 0; j < 4; j++) { accA[i][j] = 0.f; accB[i][j] = 0.f; }

    float2 cur[8];
    #pragma unroll
    for (int q = 0; q < 2; q++) {
        cur[4 * q + 0] = *(const float2*)(xr[2 * q + 0] + cofL);
        cur[4 * q + 1] = *(const float2*)(xr[2 * q + 1] + cofL);
        cur[4 * q + 2] = *(const float2*)(xr[2 * q + 0] + cofH);
        cur[4 * q + 3] = *(const float2*)(xr[2 * q + 1] + cofH);
    }

    // ============ layer 1: 4 chunks of K=64 ============
    for (int c = 0; c < 4; c++) {
        CP_WAIT0();
        __syncthreads();
        stageW(wbuf[(c + 1) & 1], gwE + (c + 1) * 8192, tid, 64);
        CP_COMMIT();
        const uint32_t wb_ = wbuf[c & 1];
        #pragma unroll
        for (int ks = 0; ks < 4; ks++) {
            uint32_t fA[4], fB[4];
            #pragma unroll
            for (int q = 0; q < 4; q++) {
                fA[q] = pk2(cur[q].x, cur[q].y);
                fB[q] = pk2(cur[4 + q].x, cur[4 + q].y);
            }
            if (!(c == 3 && ks == 3)) {
                int kb = c * 64 + (ks + 1) * 16;
                if (ks == 3) kb = (c + 1) * 64;
                #pragma unroll
                for (int q = 0; q < 2; q++) {
                    cur[4 * q + 0] = *(const float2*)(xr[2 * q + 0] + kb + cofL);
                    cur[4 * q + 1] = *(const float2*)(xr[2 * q + 1] + kb + cofL);
                    cur[4 * q + 2] = *(const float2*)(xr[2 * q + 0] + kb + cofH);
                    cur[4 * q + 3] = *(const float2*)(xr[2 * q + 1] + kb + cofH);
                }
            }
            uint32_t k0 = ks * 16;
            #pragma unroll
            for (int p = 0; p < 4; p++) {
                uint32_t boff = ((p * 16 + bRowL) * HPAD + k0 + bKof) * 2;
                uint32_t bh[4], bl[4];
                LDSM4(bh, wb_ + boff);
                LDSM4(bl, wb_ + 9216 + boff);
                MMA8I((accA + 2 * p), (accB + 2 * p), fA, fB, bh, bl);
            }
        }
    }

    // ============ layers 2..5 (stages 4..7) ============
    for (int s = 4; s < 8; s++) {
        CP_WAIT0();
        __syncthreads();
        stageW(wbuf[(s + 1) & 1], gwE + (s + 1) * 8192, tid, (s == 7) ? 32 : 64);
        CP_COMMIT();
        const float* bb = sB + (s - 4) * 64;
        uint32_t fA[4][4], fB[4][4];
        #pragma unroll
        for (int kt = 0; kt < 4; kt++) {
            #pragma unroll
            for (int h = 0; h < 2; h++) {
                int nt = 2 * kt + h;
                float b0v = bb[nt * 8 + cofL], b1v = bb[nt * 8 + cofL + 1];
                float v0 = fmaxf(accA[nt][0] + b0v, 0.f);
                float v1 = fmaxf(accA[nt][1] + b1v, 0.f);
                float v2 = fmaxf(accA[nt][2] + b0v, 0.f);
                float v3 = fmaxf(accA[nt][3] + b1v, 0.f);
                fA[kt][2 * h]     = pk2(v0, v1);
                fA[kt][2 * h + 1] = pk2(v2, v3);
                float w0 = fmaxf(accB[nt][0] + b0v, 0.f);
                float w1 = fmaxf(accB[nt][1] + b1v, 0.f);
                float w2 = fmaxf(accB[nt][2] + b0v, 0.f);
                float w3 = fmaxf(accB[nt][3] + b1v, 0.f);
                fB[kt][2 * h]     = pk2(w0, w1);
                fB[kt][2 * h + 1] = pk2(w2, w3);
            }
        }
        #pragma unroll
        for (int i = 0; i < 8; i++)
            #pragma unroll
            for (int j = 0; j < 4; j++) { accA[i][j] = 0.f; accB[i][j] = 0.f; }
        #pragma unroll
        for (int ks = 0; ks < 4; ks++) {
            uint32_t k0 = ks * 16;
            #pragma unroll
            for (int p = 0; p < 4; p++) {
                uint32_t boff = ((p * 16 + bRowL) * HPAD + k0 + bKof) * 2;
                uint32_t bh[4], bl[4];
                LDSM4(bh, wbuf[s & 1] + boff);
                LDSM4(bl, wbuf[s & 1] + 9216 + boff);
                MMA8I((accA + 2 * p), (accB + 2 * p), fA[ks], fB[ks], bh, bl);
            }
        }
    }

    // ============ layer 6 (stage 8) ============
    CP_WAIT0();
    __syncthreads();
    {
        const float* bb = sB + 256;
        uint32_t fA[4][4], fB[4][4];
        #pragma unroll
        for (int kt = 0; kt < 4; kt++) {
            #pragma unroll
            for (int h = 0; h < 2; h++) {
                int nt = 2 * kt + h;
                float b0v = bb[nt * 8 + cofL], b1v = bb[nt * 8 + cofL + 1];
                float v0 = fmaxf(accA[nt][0] + b0v, 0.f);
                float v1 = fmaxf(accA[nt][1] + b1v, 0.f);
                float v2 = fmaxf(accA[nt][2] + b0v, 0.f);
                float v3 = fmaxf(accA[nt][3] + b1v, 0.f);
                fA[kt][2 * h]     = pk2(v0, v1);
                fA[kt][2 * h + 1] = pk2(v2, v3);
                float w0 = fmaxf(accB[nt][0] + b0v, 0.f);
                float w1 = fmaxf(accB[nt][1] + b1v, 0.f);
                float w2 = fmaxf(accB[nt][2] + b0v, 0.f);
                float w3 = fmaxf(accB[nt][3] + b1v, 0.f);
                fB[kt][2 * h]     = pk2(w0, w1);
                fB[kt][2 * h + 1] = pk2(w2, w3);
            }
        }
        float acc6A[4][4], acc6B[4][4];
        #pragma unroll
        for (int i = 0; i < 4; i++)
            #pragma unroll
            for (int j = 0; j < 4; j++) { acc6A[i][j] = 0.f; acc6B[i][j] = 0.f; }

        const uint32_t wb_ = wbuf[0];
        #pragma unroll
        for (int ks = 0; ks < 4; ks++) {
            uint32_t k0 = ks * 16;
            #pragma unroll
            for (int p = 0; p < 2; p++) {
                uint32_t boff = ((p * 16 + bRowL) * HPAD + k0 + bKof) * 2;
                uint32_t bh[4], bl[4];
                LDSM4(bh, wb_ + boff);
                LDSM4(bl, wb_ + 9216 + boff);
                MMA8I((acc6A + 2 * p), (acc6B + 2 * p), fA[ks], fB[ks], bh, bl);
            }
        }

        const float* b6b = sB + 320;
        #pragma unroll
        for (int nt = 0; nt < 3; nt++) {
            int c0 = nt * 8 + cofL;
            if (c0 + 1 < ACT) {
                float b0v = b6b[c0], b1v = b6b[c0 + 1];
                if (pr[0] >= 0) {
                    out[(size_t)pr[0] * ACT + c0]     = acc6A[nt][0] + b0v;
                    out[(size_t)pr[0] * ACT + c0 + 1] = acc6A[nt][1] + b1v;
                }
                if (pr[1] >= 0) {
                    out[(size_t)pr[1] * ACT + c0]     = acc6A[nt][2] + b0v;
                    out[(size_t)pr[1] * ACT + c0 + 1] = acc6A[nt][3] + b1v;
                }
                if (pr[2] >= 0) {
                    out[(size_t)pr[2] * ACT + c0]     = acc6B[nt][0] + b0v;
                    out[(size_t)pr[2] * ACT + c0 + 1] = acc6B[nt][1] + b1v;
                }
                if (pr[3] >= 0) {
                    out[(size_t)pr[3] * ACT + c0]     = acc6B[nt][2] + b0v;
                    out[(size_t)pr[3] * ACT + c0 + 1] = acc6B[nt][3] + b1v;
                }
            }
        }
    }
}

extern "C" void kernel_launch(void* const* d_in, const int* in_sizes, int n_in,
                              void* d_out, int out_size) {
    const float* X  = (const float*)d_in[0];
    const int*   rm = (const int*)d_in[1];
    const float* W1 = (const float*)d_in[2];  const float* b1 = (const float*)d_in[3];
    const float* W2 = (const float*)d_in[4];  const float* b2 = (const float*)d_in[5];
    const float* W3 = (const float*)d_in[6];  const float* b3 = (const float*)d_in[7];
    const float* W4 = (const float*)d_in[8];  const float* b4 = (const float*)d_in[9];
    const float* W5 = (const float*)d_in[10]; const float* b5 = (const float*)d_in[11];
    const float* W6 = (const float*)d_in[12]; const float* b6 = (const float*)d_in[13];
    float* out = (float*)d_out;

    cudaFuncSetAttribute(k_moe, cudaFuncAttributeMaxDynamicSharedMemorySize, SMEM_TOTAL);

    k_pre1<<<HB + WB, 256>>>((const int4*)rm, W1, W2, W3, W4, W5, W6);
    k_scatter<<<HB, 256>>>((const int4*)rm);

    dim3 grid(NB / ROWS, NEXP);
    k_moe<<<grid, NTHR, SMEM_TOTAL>>>(X, b1, b2, b3, b4, b5, b6, out);
}

// round 12
// speedup vs baseline: 1.9473x; 1.0527x over previous
#include <cuda_runtime.h>
#include <cuda_fp16.h>
#include <cstdint>

#define NB    65536
#define DIM   256
#define HID   64
#define ACT   18
#define NEXP  8
#define ROWS  128
#define NTHR  128
#define HPAD  72        // halves per row stride (144B) -> conflict-free ldmatrix
#define TILES_PER_EXP 128   // 16384-row capacity per expert (~97 sigma margin)

// smem: W double buffer + bias
#define SWSZ   18432
#define SBIAS  (2 * SWSZ)
#define SMEM_TOTAL (SBIAS + 1408)

// ---------------- scratch ----------------
#define HB 64
__device__ int g_part[HB * NEXP];
__device__ int g_offsets[NEXP + 1];
__device__ int g_perm[NB];
// per expert 9 slots (W1 c0..c3, W2..W5, W6) of 8192 halves:
// hi plane [0,4096), lo plane [4096,8192); layout [n][64 k]
__device__ __align__(16) __half g_w[NEXP * 9 * 8192];

#define WCB (NEXP * 9)   // 72 weight-tile conversion blocks

// ---------------- fused hist + coalesced wconv ----------------
__global__ void k_pre1(const int4* __restrict__ rm,
                       const float* __restrict__ W1, const float* __restrict__ W2,
                       const float* __restrict__ W3, const float* __restrict__ W4,
                       const float* __restrict__ W5, const float* __restrict__ W6) {
    __shared__ float sm[64 * 65];
    int b = blockIdx.x, t = threadIdx.x;
    if (b < HB) {
        int* s_cnt = (int*)sm;
        if (t < NEXP) s_cnt[t] = 0;
        __syncthreads();
        int4 v = rm[b * 256 + t];
        int vv[4] = { v.x, v.y, v.z, v.w };
        #pragma unroll
        for (int r = 0; r < 4; r++) {
            unsigned m = __match_any_sync(0xffffffffu, vv[r]);
            if ((t & 31) == __ffs(m) - 1) atomicAdd(&s_cnt[vv[r]], __popc(m));
        }
        __syncthreads();
        if (t < NEXP) g_part[b * NEXP + t] = s_cnt[t];
        return;
    }
    // ---- weight tile conversion: one 64x64 (or 64x18) tile per block ----
    int s = (b - HB) % 9, e = (b - HB) / 9;
    int base = (e * 9 + s) * 8192;
    if (s < 8) {
        const float* src;
        if (s < 4)      src = W1 + (size_t)e * 16384 + s * 4096;
        else if (s == 4) src = W2 + (size_t)e * 4096;
        else if (s == 5) src = W3 + (size_t)e * 4096;
        else if (s == 6) src = W4 + (size_t)e * 4096;
        else             src = W5 + (size_t)e * 4096;
        // coalesced load [64k][64n] -> smem padded
        #pragma unroll
        for (int j = 0; j < 4; j++) {
            int f = t + j * 256;              // float4 id 0..1023
            int row = f >> 4, c4 = (f & 15) * 4;
            float4 v = *(const float4*)(src + row * 64 + c4);
            float* d = sm + row * 65 + c4;
            d[0] = v.x; d[1] = v.y; d[2] = v.z; d[3] = v.w;
        }
        __syncthreads();
        // transposed write: thread covers n = t>>2, k in [(t&3)*16, +16)
        int n = t >> 2, kb = (t & 3) * 16;
        __align__(16) __half hb[16], lb[16];
        #pragma unroll
        for (int kk = 0; kk < 16; kk++) {
            float w = sm[(kb + kk) * 65 + n];
            __half h = __float2half_rn(w);
            hb[kk] = h;
            lb[kk] = __float2half_rn(w - __half2float(h));
        }
        uint4* dh = (uint4*)&g_w[base + n * 64 + kb];
        dh[0] = *(uint4*)hb;  dh[1] = *(uint4*)(hb + 8);
        uint4* dl = (uint4*)&g_w[base + 4096 + n * 64 + kb];
        dl[0] = *(uint4*)lb;  dl[1] = *(uint4*)(lb + 8);
    } else {
        // W6: [64k][18n] -> [32n][64k] zero-padded
        const float* src6 = W6 + (size_t)e * 64 * ACT;
        for (int i = t; i < 64 * ACT; i += 256)
            sm[(i / ACT) * 65 + (i % ACT)] = src6[i];
        __syncthreads();
        int n = t >> 3, kb = (t & 7) * 8;   // 256 threads cover 32n x 64k
        __align__(16) __half hb[8], lb[8];
        #pragma unroll
        for (int kk = 0; kk < 8; kk++) {
            float w = (n < ACT) ? sm[(kb + kk) * 65 + n] : 0.f;
            __half h = __float2half_rn(w);
            hb[kk] = h;
            lb[kk] = __float2half_rn(w - __half2float(h));
        }
        *(uint4*)&g_w[base + n * 64 + kb] = *(uint4*)hb;
        *(uint4*)&g_w[base + 4096 + n * 64 + kb] = *(uint4*)lb;
    }
}

// ---------------- scatter (computes its own prefix from g_part) ----------------
__global__ void k_scatter(const int4* __restrict__ rm) {
    __shared__ int s_base[NEXP];
    __shared__ int s_cnt[NEXP];
    int b = blockIdx.x, t = threadIdx.x;
    if (t < NEXP) {
        int col = 0, pre = 0;
        #pragma unroll
        for (int bb = 0; bb < HB; bb++) {
            int v = g_part[bb * NEXP + t];
            col += v;
            if (bb < b) pre += v;
        }
        int offs = 0;
        #pragma unroll
        for (int u = 0; u < NEXP; u++) {
            int cv = __shfl_sync(0x000000ffu, col, u);
            if (u < t) offs += cv;
        }
        s_base[t] = offs + pre;
        s_cnt[t] = 0;
        if (b == 0) {
            g_offsets[t] = offs;
            if (t == NEXP - 1) g_offsets[NEXP] = offs + col;
        }
    }
    __syncthreads();
    int4 v = rm[b * 256 + t];
    int vv[4] = { v.x, v.y, v.z, v.w };
    unsigned lt = (1u << (t & 31)) - 1u;
    int i4 = (b * 256 + t) * 4;
    #pragma unroll
    for (int r = 0; r < 4; r++) {
        unsigned m = __match_any_sync(0xffffffffu, vv[r]);
        int leader = __ffs(m) - 1;
        int base = 0;
        if ((t & 31) == leader) base = atomicAdd(&s_cnt[vv[r]], __popc(m));
        base = __shfl_sync(0xffffffffu, base, leader);
        g_perm[s_base[vv[r]] + base + __popc(m & lt)] = i4 + r;
    }
}

// ---------------- helpers ----------------
__device__ __forceinline__ uint32_t smem_u32(const void* p) {
    uint32_t a;
    asm("{ .reg .u64 t; cvta.to.shared.u64 t, %1; cvt.u32.u64 %0, t; }" : "=r"(a) : "l"(p));
    return a;
}
// pack: {lo16 = f16(a), hi16 = f16(b)}
__device__ __forceinline__ uint32_t pk2(float a, float b) {
    uint32_t r;
    asm("cvt.rn.f16x2.f32 %0, %1, %2;" : "=r"(r) : "f"(b), "f"(a));
    return r;
}
#define CP16(dst, src) \
    asm volatile("cp.async.ca.shared.global [%0], [%1], 16;" :: "r"(dst), "l"(src))
#define CP_COMMIT() asm volatile("cp.async.commit_group;" ::: "memory")
#define CP_WAIT0()  asm volatile("cp.async.wait_group 0;" ::: "memory")

#define LDSM4(d, addr) \
    asm volatile("ldmatrix.sync.aligned.m8n8.x4.shared.b16 {%0,%1,%2,%3}, [%4];" \
        : "=r"((d)[0]), "=r"((d)[1]), "=r"((d)[2]), "=r"((d)[3]) : "r"(addr))

// non-volatile: ptxas may interleave/software-pipeline the MMA stream
#define MMA(c, a, b0, b1) \
    asm("mma.sync.aligned.m16n8k16.row.col.f32.f16.f16.f32 " \
        "{%0,%1,%2,%3},{%4,%5,%6,%7},{%8,%9},{%0,%1,%2,%3};" \
        : "+f"((c)[0]), "+f"((c)[1]), "+f"((c)[2]), "+f"((c)[3]) \
        : "r"((a)[0]), "r"((a)[1]), "r"((a)[2]), "r"((a)[3]), "r"(b0), "r"(b1))

__device__ __forceinline__ void stageW(uint32_t swb, const __half* gw,
                                       int tid, int nW) {
    const char* src = (const char*)gw;
    int total = nW * 8;
    #pragma unroll 4
    for (int i = tid; i < total; i += NTHR) {
        int n = i >> 3, j = i & 7;
        uint32_t d = n * (HPAD * 2) + j * 16;
        int s = (n * 64 + j * 8) * 2;
        CP16(swb + d, src + s);
        CP16(swb + 9216 + d, src + 8192 + s);
    }
}

// 8 MMAs interleaved over 4 independent accumulator chains
#define MMA8I(aA, aB, fA, fB, bh, bl) do {               \
    MMA((aA)[0], fA, (bh)[0], (bh)[1]);                  \
    MMA((aA)[1], fA, (bh)[2], (bh)[3]);                  \
    MMA((aB)[0], fB, (bh)[0], (bh)[1]);                  \
    MMA((aB)[1], fB, (bh)[2], (bh)[3]);                  \
    MMA((aA)[0], fA, (bl)[0], (bl)[1]);                  \
    MMA((aA)[1], fA, (bl)[2], (bl)[3]);                  \
    MMA((aB)[0], fB, (bl)[0], (bl)[1]);                  \
    MMA((aB)[1], fB, (bl)[2], (bl)[3]);                  \
} while (0)

// ---------------- fused MoE (32 rows/warp, fp16 2-term) ----------------
__global__ void __launch_bounds__(NTHR, 4) k_moe(
    const float* __restrict__ X,
    const float* __restrict__ b1, const float* __restrict__ b2,
    const float* __restrict__ b3, const float* __restrict__ b4,
    const float* __restrict__ b5, const float* __restrict__ b6,
    float* __restrict__ out)
{
    extern __shared__ char smem[];
    const int tid = threadIdx.x, wid = tid >> 5, lane = tid & 31;
    const int e = blockIdx.y, tile = blockIdx.x;
    const int off = g_offsets[e];
    const int cnt = g_offsets[e + 1] - off;
    if (tile * ROWS >= cnt) return;
    const int nrows = min(ROWS, cnt - tile * ROWS);

    const uint32_t sb = smem_u32(smem);
    const uint32_t wbuf[2] = { sb, sb + SWSZ };
    float* sB = (float*)(smem + SBIAS);

    const __half* gwE = g_w + (size_t)e * 9 * 8192;

    stageW(wbuf[0], gwE, tid, 64);
    CP_COMMIT();

    if (tid < 64) {
        sB[tid]       = b1[e * HID + tid];
        sB[64 + tid]  = b2[e * HID + tid];
        sB[128 + tid] = b3[e * HID + tid];
        sB[192 + tid] = b4[e * HID + tid];
        sB[256 + tid] = b5[e * HID + tid];
    }
    if (tid < 32) sB[320 + tid] = (tid < ACT) ? b6[e * ACT + tid] : 0.f;

    const uint32_t bRowL = (uint32_t)((lane & 7) + ((lane >> 4) & 1) * 8);
    const uint32_t bKof  = ((lane >> 3) & 1) * 8;

    const int erow = wid * 32 + (lane >> 2);
    int pr[4];
    const float* xr[4];
    #pragma unroll
    for (int q = 0; q < 4; q++) {
        int rr = erow + q * 8;
        pr[q] = (rr < nrows) ? g_perm[off + tile * ROWS + rr] : -1;
        xr[q] = X + (size_t)((pr[q] >= 0) ? pr[q] : g_perm[off]) * DIM;
    }
    const int cofL = (lane & 3) * 2;
    const int cofH = 8 + cofL;

    float accA[8][4], accB[8][4];
    #pragma unroll
    for (int i = 0; i < 8; i++)
        #pragma unroll
        for (int j = 0; j < 4; j++) { accA[i][j] = 0.f; accB[i][j] = 0.f; }

    float2 cur[8];
    #pragma unroll
    for (int q = 0; q < 2; q++) {
        cur[4 * q + 0] = *(const float2*)(xr[2 * q + 0] + cofL);
        cur[4 * q + 1] = *(const float2*)(xr[2 * q + 1] + cofL);
        cur[4 * q + 2] = *(const float2*)(xr[2 * q + 0] + cofH);
        cur[4 * q + 3] = *(const float2*)(xr[2 * q + 1] + cofH);
    }

    // ============ layer 1: 4 chunks of K=64 ============
    for (int c = 0; c < 4; c++) {
        CP_WAIT0();
        __syncthreads();
        stageW(wbuf[(c + 1) & 1], gwE + (c + 1) * 8192, tid, 64);
        CP_COMMIT();
        const uint32_t wb_ = wbuf[c & 1];
        #pragma unroll
        for (int ks = 0; ks < 4; ks++) {
            uint32_t fA[4], fB[4];
            #pragma unroll
            for (int q = 0; q < 4; q++) {
                fA[q] = pk2(cur[q].x, cur[q].y);
                fB[q] = pk2(cur[4 + q].x, cur[4 + q].y);
            }
            if (!(c == 3 && ks == 3)) {
                int kb = c * 64 + (ks + 1) * 16;
                if (ks == 3) kb = (c + 1) * 64;
                #pragma unroll
                for (int q = 0; q < 2; q++) {
                    cur[4 * q + 0] = *(const float2*)(xr[2 * q + 0] + kb + cofL);
                    cur[4 * q + 1] = *(const float2*)(xr[2 * q + 1] + kb + cofL);
                    cur[4 * q + 2] = *(const float2*)(xr[2 * q + 0] + kb + cofH);
                    cur[4 * q + 3] = *(const float2*)(xr[2 * q + 1] + kb + cofH);
                }
            }
            uint32_t k0 = ks * 16;
            #pragma unroll
            for (int p = 0; p < 4; p++) {
                uint32_t boff = ((p * 16 + bRowL) * HPAD + k0 + bKof) * 2;
                uint32_t bh[4], bl[4];
                LDSM4(bh, wb_ + boff);
                LDSM4(bl, wb_ + 9216 + boff);
                MMA8I((accA + 2 * p), (accB + 2 * p), fA, fB, bh, bl);
            }
        }
    }

    // ============ layers 2..5 (stages 4..7) ============
    for (int s = 4; s < 8; s++) {
        CP_WAIT0();
        __syncthreads();
        stageW(wbuf[(s + 1) & 1], gwE + (s + 1) * 8192, tid, (s == 7) ? 32 : 64);
        CP_COMMIT();
        const float* bb = sB + (s - 4) * 64;
        uint32_t fA[4][4], fB[4][4];
        #pragma unroll
        for (int kt = 0; kt < 4; kt++) {
            #pragma unroll
            for (int h = 0; h < 2; h++) {
                int nt = 2 * kt + h;
                float b0v = bb[nt * 8 + cofL], b1v = bb[nt * 8 + cofL + 1];
                float v0 = fmaxf(accA[nt][0] + b0v, 0.f);
                float v1 = fmaxf(accA[nt][1] + b1v, 0.f);
                float v2 = fmaxf(accA[nt][2] + b0v, 0.f);
                float v3 = fmaxf(accA[nt][3] + b1v, 0.f);
                fA[kt][2 * h]     = pk2(v0, v1);
                fA[kt][2 * h + 1] = pk2(v2, v3);
                float w0 = fmaxf(accB[nt][0] + b0v, 0.f);
                float w1 = fmaxf(accB[nt][1] + b1v, 0.f);
                float w2 = fmaxf(accB[nt][2] + b0v, 0.f);
                float w3 = fmaxf(accB[nt][3] + b1v, 0.f);
                fB[kt][2 * h]     = pk2(w0, w1);
                fB[kt][2 * h + 1] = pk2(w2, w3);
            }
        }
        #pragma unroll
        for (int i = 0; i < 8; i++)
            #pragma unroll
            for (int j = 0; j < 4; j++) { accA[i][j] = 0.f; accB[i][j] = 0.f; }
        #pragma unroll
        for (int ks = 0; ks < 4; ks++) {
            uint32_t k0 = ks * 16;
            #pragma unroll
            for (int p = 0; p < 4; p++) {
                uint32_t boff = ((p * 16 + bRowL) * HPAD + k0 + bKof) * 2;
                uint32_t bh[4], bl[4];
                LDSM4(bh, wbuf[s & 1] + boff);
                LDSM4(bl, wbuf[s & 1] + 9216 + boff);
                MMA8I((accA + 2 * p), (accB + 2 * p), fA[ks], fB[ks], bh, bl);
            }
        }
    }

    // ============ layer 6 (stage 8) ============
    CP_WAIT0();
    __syncthreads();
    {
        const float* bb = sB + 256;
        uint32_t fA[4][4], fB[4][4];
        #pragma unroll
        for (int kt = 0; kt < 4; kt++) {
            #pragma unroll
            for (int h = 0; h < 2; h++) {
                int nt = 2 * kt + h;
                float b0v = bb[nt * 8 + cofL], b1v = bb[nt * 8 + cofL + 1];
                float v0 = fmaxf(accA[nt][0] + b0v, 0.f);
                float v1 = fmaxf(accA[nt][1] + b1v, 0.f);
                float v2 = fmaxf(accA[nt][2] + b0v, 0.f);
                float v3 = fmaxf(accA[nt][3] + b1v, 0.f);
                fA[kt][2 * h]     = pk2(v0, v1);
                fA[kt][2 * h + 1] = pk2(v2, v3);
                float w0 = fmaxf(accB[nt][0] + b0v, 0.f);
                float w1 = fmaxf(accB[nt][1] + b1v, 0.f);
                float w2 = fmaxf(accB[nt][2] + b0v, 0.f);
                float w3 = fmaxf(accB[nt][3] + b1v, 0.f);
                fB[kt][2 * h]     = pk2(w0, w1);
                fB[kt][2 * h + 1] = pk2(w2, w3);
            }
        }
        float acc6A[4][4], acc6B[4][4];
        #pragma unroll
        for (int i = 0; i < 4; i++)
            #pragma unroll
            for (int j = 0; j < 4; j++) { acc6A[i][j] = 0.f; acc6B[i][j] = 0.f; }

        const uint32_t wb_ = wbuf[0];
        #pragma unroll
        for (int ks = 0; ks < 4; ks++) {
            uint32_t k0 = ks * 16;
            #pragma unroll
            for (int p = 0; p < 2; p++) {
                uint32_t boff = ((p * 16 + bRowL) * HPAD + k0 + bKof) * 2;
                uint32_t bh[4], bl[4];
                LDSM4(bh, wb_ + boff);
                LDSM4(bl, wb_ + 9216 + boff);
                MMA8I((acc6A + 2 * p), (acc6B + 2 * p), fA[ks], fB[ks], bh, bl);
            }
        }

        const float* b6b = sB + 320;
        #pragma unroll
        for (int nt = 0; nt < 3; nt++) {
            int c0 = nt * 8 + cofL;
            if (c0 + 1 < ACT) {
                float b0v = b6b[c0], b1v = b6b[c0 + 1];
                if (pr[0] >= 0) {
                    out[(size_t)pr[0] * ACT + c0]     = acc6A[nt][0] + b0v;
                    out[(size_t)pr[0] * ACT + c0 + 1] = acc6A[nt][1] + b1v;
                }
                if (pr[1] >= 0) {
                    out[(size_t)pr[1] * ACT + c0]     = acc6A[nt][2] + b0v;
                    out[(size_t)pr[1] * ACT + c0 + 1] = acc6A[nt][3] + b1v;
                }
                if (pr[2] >= 0) {
                    out[(size_t)pr[2] * ACT + c0]     = acc6B[nt][0] + b0v;
                    out[(size_t)pr[2] * ACT + c0 + 1] = acc6B[nt][1] + b1v;
                }
                if (pr[3] >= 0) {
                    out[(size_t)pr[3] * ACT + c0]     = acc6B[nt][2] + b0v;
                    out[(size_t)pr[3] * ACT + c0 + 1] = acc6B[nt][3] + b1v;
                }
            }
        }
    }
}

extern "C" void kernel_launch(void* const* d_in, const int* in_sizes, int n_in,
                              void* d_out, int out_size) {
    const float* X  = (const float*)d_in[0];
    const int*   rm = (const int*)d_in[1];
    const float* W1 = (const float*)d_in[2];  const float* b1 = (const float*)d_in[3];
    const float* W2 = (const float*)d_in[4];  const float* b2 = (const float*)d_in[5];
    const float* W3 = (const float*)d_in[6];  const float* b3 = (const float*)d_in[7];
    const float* W4 = (const float*)d_in[8];  const float* b4 = (const float*)d_in[9];
    const float* W5 = (const float*)d_in[10]; const float* b5 = (const float*)d_in[11];
    const float* W6 = (const float*)d_in[12]; const float* b6 = (const float*)d_in[13];
    float* out = (float*)d_out;

    cudaFuncSetAttribute(k_moe, cudaFuncAttributeMaxDynamicSharedMemorySize, SMEM_TOTAL);

    k_pre1<<<HB + WCB, 256>>>((const int4*)rm, W1, W2, W3, W4, W5, W6);
    k_scatter<<<HB, 256>>>((const int4*)rm);

    dim3 grid(TILES_PER_EXP, NEXP);
    k_moe<<<grid, NTHR, SMEM_TOTAL>>>(X, b1, b2, b3, b4, b5, b6, out);
}

// round 13
// speedup vs baseline: 2.0274x; 1.0412x over previous
#include <cuda_runtime.h>
#include <cuda_fp16.h>
#include <cstdint>

#define NB    65536
#define DIM   256
#define HID   64
#define ACT   18
#define NEXP  8
#define ROWS  128
#define NTHR  128
#define HPAD  72        // halves per row stride (144B) -> conflict-free ldmatrix
#define TILES_PER_EXP 128

// smem: W double buffer + bias
#define SWSZ   18432
#define SBIAS  (2 * SWSZ)
#define SMEM_TOTAL (SBIAS + 1408)

// ---------------- scratch ----------------
#define HB 64
__device__ int g_part[HB * NEXP];
__device__ int g_offsets[NEXP + 1];
__device__ int g_perm[NB];
// per expert 9 slots (W1 c0..c3, W2..W5, W6) of 8192 halves:
// hi plane [0,4096), lo plane [4096,8192); layout [n][64 k]
__device__ __align__(16) __half g_w[NEXP * 9 * 8192];

#define WCB (NEXP * 9)   // 72 weight-tile conversion blocks

// ---------------- launch 1: histogram only (fast) ----------------
__global__ void k_hist(const int4* __restrict__ rm) {
    __shared__ int s_cnt[NEXP];
    int b = blockIdx.x, t = threadIdx.x;
    if (t < NEXP) s_cnt[t] = 0;
    __syncthreads();
    int4 v = rm[b * 256 + t];
    int vv[4] = { v.x, v.y, v.z, v.w };
    #pragma unroll
    for (int r = 0; r < 4; r++) {
        unsigned m = __match_any_sync(0xffffffffu, vv[r]);
        if ((t & 31) == __ffs(m) - 1) atomicAdd(&s_cnt[vv[r]], __popc(m));
    }
    __syncthreads();
    if (t < NEXP) g_part[b * NEXP + t] = s_cnt[t];
}

// ---------------- launch 2: scatter (blocks 0..63)  ||  wconv (blocks 64..135) ----------------
__global__ void k_pre2(const int4* __restrict__ rm,
                       const float* __restrict__ W1, const float* __restrict__ W2,
                       const float* __restrict__ W3, const float* __restrict__ W4,
                       const float* __restrict__ W5, const float* __restrict__ W6) {
    __shared__ float sm[64 * 65];
    int b = blockIdx.x, t = threadIdx.x;
    if (b < HB) {
        // ---- scatter: computes its own prefix from g_part ----
        int* s_base = (int*)sm;
        int* s_cnt  = (int*)sm + NEXP;
        if (t < NEXP) {
            int col = 0, pre = 0;
            #pragma unroll
            for (int bb = 0; bb < HB; bb++) {
                int v = g_part[bb * NEXP + t];
                col += v;
                if (bb < b) pre += v;
            }
            int offs = 0;
            #pragma unroll
            for (int u = 0; u < NEXP; u++) {
                int cv = __shfl_sync(0x000000ffu, col, u);
                if (u < t) offs += cv;
            }
            s_base[t] = offs + pre;
            s_cnt[t] = 0;
            if (b == 0) {
                g_offsets[t] = offs;
                if (t == NEXP - 1) g_offsets[NEXP] = offs + col;
            }
        }
        __syncthreads();
        int4 v = rm[b * 256 + t];
        int vv[4] = { v.x, v.y, v.z, v.w };
        unsigned lt = (1u << (t & 31)) - 1u;
        int i4 = (b * 256 + t) * 4;
        #pragma unroll
        for (int r = 0; r < 4; r++) {
            unsigned m = __match_any_sync(0xffffffffu, vv[r]);
            int leader = __ffs(m) - 1;
            int base = 0;
            if ((t & 31) == leader) base = atomicAdd(&s_cnt[vv[r]], __popc(m));
            base = __shfl_sync(0xffffffffu, base, leader);
            g_perm[s_base[vv[r]] + base + __popc(m & lt)] = i4 + r;
        }
        return;
    }
    // ---- weight tile conversion: one 64x64 (or 64x18) tile per block ----
    int s = (b - HB) % 9, e = (b - HB) / 9;
    int base = (e * 9 + s) * 8192;
    if (s < 8) {
        const float* src;
        if (s < 4)       src = W1 + (size_t)e * 16384 + s * 4096;
        else if (s == 4) src = W2 + (size_t)e * 4096;
        else if (s == 5) src = W3 + (size_t)e * 4096;
        else if (s == 6) src = W4 + (size_t)e * 4096;
        else             src = W5 + (size_t)e * 4096;
        #pragma unroll
        for (int j = 0; j < 4; j++) {
            int f = t + j * 256;
            int row = f >> 4, c4 = (f & 15) * 4;
            float4 v = *(const float4*)(src + row * 64 + c4);
            float* d = sm + row * 65 + c4;
            d[0] = v.x; d[1] = v.y; d[2] = v.z; d[3] = v.w;
        }
        __syncthreads();
        int n = t >> 2, kb = (t & 3) * 16;
        __align__(16) __half hb[16], lb[16];
        #pragma unroll
        for (int kk = 0; kk < 16; kk++) {
            float w = sm[(kb + kk) * 65 + n];
            __half h = __float2half_rn(w);
            hb[kk] = h;
            lb[kk] = __float2half_rn(w - __half2float(h));
        }
        uint4* dh = (uint4*)&g_w[base + n * 64 + kb];
        dh[0] = *(uint4*)hb;  dh[1] = *(uint4*)(hb + 8);
        uint4* dl = (uint4*)&g_w[base + 4096 + n * 64 + kb];
        dl[0] = *(uint4*)lb;  dl[1] = *(uint4*)(lb + 8);
    } else {
        const float* src6 = W6 + (size_t)e * 64 * ACT;
        for (int i = t; i < 64 * ACT; i += 256)
            sm[(i / ACT) * 65 + (i % ACT)] = src6[i];
        __syncthreads();
        int n = t >> 3, kb = (t & 7) * 8;
        __align__(16) __half hb[8], lb[8];
        #pragma unroll
        for (int kk = 0; kk < 8; kk++) {
            float w = (n < ACT) ? sm[(kb + kk) * 65 + n] : 0.f;
            __half h = __float2half_rn(w);
            hb[kk] = h;
            lb[kk] = __float2half_rn(w - __half2float(h));
        }
        *(uint4*)&g_w[base + n * 64 + kb] = *(uint4*)hb;
        *(uint4*)&g_w[base + 4096 + n * 64 + kb] = *(uint4*)lb;
    }
}

// ---------------- helpers ----------------
__device__ __forceinline__ uint32_t smem_u32(const void* p) {
    uint32_t a;
    asm("{ .reg .u64 t; cvta.to.shared.u64 t, %1; cvt.u32.u64 %0, t; }" : "=r"(a) : "l"(p));
    return a;
}
// pack: {lo16 = f16(a), hi16 = f16(b)}
__device__ __forceinline__ uint32_t pk2(float a, float b) {
    uint32_t r;
    asm("cvt.rn.f16x2.f32 %0, %1, %2;" : "=r"(r) : "f"(b), "f"(a));
    return r;
}
#define CP16(dst, src) \
    asm volatile("cp.async.ca.shared.global [%0], [%1], 16;" :: "r"(dst), "l"(src))
#define CP_COMMIT() asm volatile("cp.async.commit_group;" ::: "memory")
#define CP_WAIT0()  asm volatile("cp.async.wait_group 0;" ::: "memory")

#define LDSM4(d, addr) \
    asm volatile("ldmatrix.sync.aligned.m8n8.x4.shared.b16 {%0,%1,%2,%3}, [%4];" \
        : "=r"((d)[0]), "=r"((d)[1]), "=r"((d)[2]), "=r"((d)[3]) : "r"(addr))

// non-volatile: ptxas may interleave/software-pipeline the MMA stream
#define MMA(c, a, b0, b1) \
    asm("mma.sync.aligned.m16n8k16.row.col.f32.f16.f16.f32 " \
        "{%0,%1,%2,%3},{%4,%5,%6,%7},{%8,%9},{%0,%1,%2,%3};" \
        : "+f"((c)[0]), "+f"((c)[1]), "+f"((c)[2]), "+f"((c)[3]) \
        : "r"((a)[0]), "r"((a)[1]), "r"((a)[2]), "r"((a)[3]), "r"(b0), "r"(b1))

__device__ __forceinline__ void stageW(uint32_t swb, const __half* gw,
                                       int tid, int nW) {
    const char* src = (const char*)gw;
    int total = nW * 8;
    #pragma unroll 4
    for (int i = tid; i < total; i += NTHR) {
        int n = i >> 3, j = i & 7;
        uint32_t d = n * (HPAD * 2) + j * 16;
        int s = (n * 64 + j * 8) * 2;
        CP16(swb + d, src + s);
        CP16(swb + 9216 + d, src + 8192 + s);
    }
}

// 8 MMAs interleaved over 4 independent accumulator chains
#define MMA8I(aA, aB, fA, fB, bh, bl) do {               \
    MMA((aA)[0], fA, (bh)[0], (bh)[1]);                  \
    MMA((aA)[1], fA, (bh)[2], (bh)[3]);                  \
    MMA((aB)[0], fB, (bh)[0], (bh)[1]);                  \
    MMA((aB)[1], fB, (bh)[2], (bh)[3]);                  \
    MMA((aA)[0], fA, (bl)[0], (bl)[1]);                  \
    MMA((aA)[1], fA, (bl)[2], (bl)[3]);                  \
    MMA((aB)[0], fB, (bl)[0], (bl)[1]);                  \
    MMA((aB)[1], fB, (bl)[2], (bl)[3]);                  \
} while (0)

// ---------------- fused MoE (32 rows/warp, fp16 2-term) ----------------
__global__ void __launch_bounds__(NTHR, 4) k_moe(
    const float* __restrict__ X,
    const float* __restrict__ b1, const float* __restrict__ b2,
    const float* __restrict__ b3, const float* __restrict__ b4,
    const float* __restrict__ b5, const float* __restrict__ b6,
    float* __restrict__ out)
{
    extern __shared__ char smem[];
    const int tid = threadIdx.x, wid = tid >> 5, lane = tid & 31;
    const int e = blockIdx.y, tile = blockIdx.x;
    const int off = g_offsets[e];
    const int cnt = g_offsets[e + 1] - off;
    if (tile * ROWS >= cnt) return;
    const int nrows = min(ROWS, cnt - tile * ROWS);

    const uint32_t sb = smem_u32(smem);
    const uint32_t wbuf[2] = { sb, sb + SWSZ };
    float* sB = (float*)(smem + SBIAS);

    const __half* gwE = g_w + (size_t)e * 9 * 8192;

    stageW(wbuf[0], gwE, tid, 64);
    CP_COMMIT();

    if (tid < 64) {
        sB[tid]       = b1[e * HID + tid];
        sB[64 + tid]  = b2[e * HID + tid];
        sB[128 + tid] = b3[e * HID + tid];
        sB[192 + tid] = b4[e * HID + tid];
        sB[256 + tid] = b5[e * HID + tid];
    }
    if (tid < 32) sB[320 + tid] = (tid < ACT) ? b6[e * ACT + tid] : 0.f;

    const uint32_t bRowL = (uint32_t)((lane & 7) + ((lane >> 4) & 1) * 8);
    const uint32_t bKof  = ((lane >> 3) & 1) * 8;

    const int erow = wid * 32 + (lane >> 2);
    int pr[4];
    const float* xr[4];
    #pragma unroll
    for (int q = 0; q < 4; q++) {
        int rr = erow + q * 8;
        pr[q] = (rr < nrows) ? g_perm[off + tile * ROWS + rr] : -1;
        xr[q] = X + (size_t)((pr[q] >= 0) ? pr[q] : g_perm[off]) * DIM;
    }
    const int cofL = (lane & 3) * 2;
    const int cofH = 8 + cofL;

    float accA[8][4], accB[8][4];
    #pragma unroll
    for (int i = 0; i < 8; i++)
        #pragma unroll
        for (int j = 0; j < 4; j++) { accA[i][j] = 0.f; accB[i][j] = 0.f; }

    float2 cur[8];
    #pragma unroll
    for (int q = 0; q < 2; q++) {
        cur[4 * q + 0] = *(const float2*)(xr[2 * q + 0] + cofL);
        cur[4 * q + 1] = *(const float2*)(xr[2 * q + 1] + cofL);
        cur[4 * q + 2] = *(const float2*)(xr[2 * q + 0] + cofH);
        cur[4 * q + 3] = *(const float2*)(xr[2 * q + 1] + cofH);
    }

    // ============ layer 1: 4 chunks of K=64 ============
    for (int c = 0; c < 4; c++) {
        CP_WAIT0();
        __syncthreads();
        stageW(wbuf[(c + 1) & 1], gwE + (c + 1) * 8192, tid, 64);
        CP_COMMIT();
        const uint32_t wb_ = wbuf[c & 1];
        #pragma unroll
        for (int ks = 0; ks < 4; ks++) {
            uint32_t fA[4], fB[4];
            #pragma unroll
            for (int q = 0; q < 4; q++) {
                fA[q] = pk2(cur[q].x, cur[q].y);
                fB[q] = pk2(cur[4 + q].x, cur[4 + q].y);
            }
            if (!(c == 3 && ks == 3)) {
                int kb = c * 64 + (ks + 1) * 16;
                if (ks == 3) kb = (c + 1) * 64;
                #pragma unroll
                for (int q = 0; q < 2; q++) {
                    cur[4 * q + 0] = *(const float2*)(xr[2 * q + 0] + kb + cofL);
                    cur[4 * q + 1] = *(const float2*)(xr[2 * q + 1] + kb + cofL);
                    cur[4 * q + 2] = *(const float2*)(xr[2 * q + 0] + kb + cofH);
                    cur[4 * q + 3] = *(const float2*)(xr[2 * q + 1] + kb + cofH);
                }
            }
            uint32_t k0 = ks * 16;
            #pragma unroll
            for (int p = 0; p < 4; p++) {
                uint32_t boff = ((p * 16 + bRowL) * HPAD + k0 + bKof) * 2;
                uint32_t bh[4], bl[4];
                LDSM4(bh, wb_ + boff);
                LDSM4(bl, wb_ + 9216 + boff);
                MMA8I((accA + 2 * p), (accB + 2 * p), fA, fB, bh, bl);
            }
        }
    }

    // ============ layers 2..5 (stages 4..7) ============
    for (int s = 4; s < 8; s++) {
        CP_WAIT0();
        __syncthreads();
        stageW(wbuf[(s + 1) & 1], gwE + (s + 1) * 8192, tid, (s == 7) ? 32 : 64);
        CP_COMMIT();
        const float* bb = sB + (s - 4) * 64;
        uint32_t fA[4][4], fB[4][4];
        #pragma unroll
        for (int kt = 0; kt < 4; kt++) {
            #pragma unroll
            for (int h = 0; h < 2; h++) {
                int nt = 2 * kt + h;
                float b0v = bb[nt * 8 + cofL], b1v = bb[nt * 8 + cofL + 1];
                float v0 = fmaxf(accA[nt][0] + b0v, 0.f);
                float v1 = fmaxf(accA[nt][1] + b1v, 0.f);
                float v2 = fmaxf(accA[nt][2] + b0v, 0.f);
                float v3 = fmaxf(accA[nt][3] + b1v, 0.f);
                fA[kt][2 * h]     = pk2(v0, v1);
                fA[kt][2 * h + 1] = pk2(v2, v3);
                float w0 = fmaxf(accB[nt][0] + b0v, 0.f);
                float w1 = fmaxf(accB[nt][1] + b1v, 0.f);
                float w2 = fmaxf(accB[nt][2] + b0v, 0.f);
                float w3 = fmaxf(accB[nt][3] + b1v, 0.f);
                fB[kt][2 * h]     = pk2(w0, w1);
                fB[kt][2 * h + 1] = pk2(w2, w3);
            }
        }
        #pragma unroll
        for (int i = 0; i < 8; i++)
            #pragma unroll
            for (int j = 0; j < 4; j++) { accA[i][j] = 0.f; accB[i][j] = 0.f; }
        #pragma unroll
        for (int ks = 0; ks < 4; ks++) {
            uint32_t k0 = ks * 16;
            #pragma unroll
            for (int p = 0; p < 4; p++) {
                uint32_t boff = ((p * 16 + bRowL) * HPAD + k0 + bKof) * 2;
                uint32_t bh[4], bl[4];
                LDSM4(bh, wbuf[s & 1] + boff);
                LDSM4(bl, wbuf[s & 1] + 9216 + boff);
                MMA8I((accA + 2 * p), (accB + 2 * p), fA[ks], fB[ks], bh, bl);
            }
        }
    }

    // ============ layer 6 (stage 8) ============
    CP_WAIT0();
    __syncthreads();
    {
        const float* bb = sB + 256;
        uint32_t fA[4][4], fB[4][4];
        #pragma unroll
        for (int kt = 0; kt < 4; kt++) {
            #pragma unroll
            for (int h = 0; h < 2; h++) {
                int nt = 2 * kt + h;
                float b0v = bb[nt * 8 + cofL], b1v = bb[nt * 8 + cofL + 1];
                float v0 = fmaxf(accA[nt][0] + b0v, 0.f);
                float v1 = fmaxf(accA[nt][1] + b1v, 0.f);
                float v2 = fmaxf(accA[nt][2] + b0v, 0.f);
                float v3 = fmaxf(accA[nt][3] + b1v, 0.f);
                fA[kt][2 * h]     = pk2(v0, v1);
                fA[kt][2 * h + 1] = pk2(v2, v3);
                float w0 = fmaxf(accB[nt][0] + b0v, 0.f);
                float w1 = fmaxf(accB[nt][1] + b1v, 0.f);
                float w2 = fmaxf(accB[nt][2] + b0v, 0.f);
                float w3 = fmaxf(accB[nt][3] + b1v, 0.f);
                fB[kt][2 * h]     = pk2(w0, w1);
                fB[kt][2 * h + 1] = pk2(w2, w3);
            }
        }
        float acc6A[4][4], acc6B[4][4];
        #pragma unroll
        for (int i = 0; i < 4; i++)
            #pragma unroll
            for (int j = 0; j < 4; j++) { acc6A[i][j] = 0.f; acc6B[i][j] = 0.f; }

        const uint32_t wb_ = wbuf[0];
        #pragma unroll
        for (int ks = 0; ks < 4; ks++) {
            uint32_t k0 = ks * 16;
            #pragma unroll
            for (int p = 0; p < 2; p++) {
                uint32_t boff = ((p * 16 + bRowL) * HPAD + k0 + bKof) * 2;
                uint32_t bh[4], bl[4];
                LDSM4(bh, wb_ + boff);
                LDSM4(bl, wb_ + 9216 + boff);
                MMA8I((acc6A + 2 * p), (acc6B + 2 * p), fA[ks], fB[ks], bh, bl);
            }
        }

        const float* b6b = sB + 320;
        #pragma unroll
        for (int nt = 0; nt < 3; nt++) {
            int c0 = nt * 8 + cofL;
            if (c0 + 1 < ACT) {
                float b0v = b6b[c0], b1v = b6b[c0 + 1];
                if (pr[0] >= 0) {
                    out[(size_t)pr[0] * ACT + c0]     = acc6A[nt][0] + b0v;
                    out[(size_t)pr[0] * ACT + c0 + 1] = acc6A[nt][1] + b1v;
                }
                if (pr[1] >= 0) {
                    out[(size_t)pr[1] * ACT + c0]     = acc6A[nt][2] + b0v;
                    out[(size_t)pr[1] * ACT + c0 + 1] = acc6A[nt][3] + b1v;
                }
                if (pr[2] >= 0) {
                    out[(size_t)pr[2] * ACT + c0]     = acc6B[nt][0] + b0v;
                    out[(size_t)pr[2] * ACT + c0 + 1] = acc6B[nt][1] + b1v;
                }
                if (pr[3] >= 0) {
                    out[(size_t)pr[3] * ACT + c0]     = acc6B[nt][2] + b0v;
                    out[(size_t)pr[3] * ACT + c0 + 1] = acc6B[nt][3] + b1v;
                }
            }
        }
    }
}

extern "C" void kernel_launch(void* const* d_in, const int* in_sizes, int n_in,
                              void* d_out, int out_size) {
    const float* X  = (const float*)d_in[0];
    const int*   rm = (const int*)d_in[1];
    const float* W1 = (const float*)d_in[2];  const float* b1 = (const float*)d_in[3];
    const float* W2 = (const float*)d_in[4];  const float* b2 = (const float*)d_in[5];
    const float* W3 = (const float*)d_in[6];  const float* b3 = (const float*)d_in[7];
    const float* W4 = (const float*)d_in[8];  const float* b4 = (const float*)d_in[9];
    const float* W5 = (const float*)d_in[10]; const float* b5 = (const float*)d_in[11];
    const float* W6 = (const float*)d_in[12]; const float* b6 = (const float*)d_in[13];
    float* out = (float*)d_out;

    cudaFuncSetAttribute(k_moe, cudaFuncAttributeMaxDynamicSharedMemorySize, SMEM_TOTAL);

    k_hist<<<HB, 256>>>((const int4*)rm);
    k_pre2<<<HB + WCB, 256>>>((const int4*)rm, W1, W2, W3, W4, W5, W6);

    dim3 grid(TILES_PER_EXP, NEXP);
    k_moe<<<grid, NTHR, SMEM_TOTAL>>>(X, b1, b2, b3, b4, b5, b6, out);
}